// round 1
// baseline (speedup 1.0000x reference)
#include <cuda_runtime.h>
#include <math.h>

#define NN   10000
#define GG   200
#define ELn  160000
#define EGn  500000
#define SS   256
#define NAn  16
#define NBn  5

// ---- output offsets (floats) ----
#define OFF_CP   0           // coords_pred  (N,3)
#define OFF_CE0  30000       // coords_eps0  (N,3)
#define OFF_AP   60000       // atoms_pred   (N,16)
#define OFF_AE   220000      // atoms_eps    (N,16)
#define OFF_BP   380000      // bonds_pred   (EG,5)
#define OFF_BE   2880000     // bonds_eps    (EG,5)
#define OFF_DL   5380000     // d_l          (EL,)
#define OFF_RNL  5540000     // rn_l         (EL,3)
#define OFF_AG   6020000     // a_g          (EG,)
#define OFF_RNG  6520000     // rn_g         (EG,3)

// ---- scratch (device globals; no allocation allowed) ----
__device__ float g_sum[GG * 3];
__device__ float g_cnt[GG];
__device__ float g_temb[GG * SS];
__device__ float g_posc[NN * 3];
__device__ float g_bufA[NN * SS];
__device__ float g_bufB[NN * SS];
__device__ float g_zbias[SS];

// ============================================================
// K0: zero per-graph accumulators + time embedding + zero bias
// ============================================================
__global__ void k_init(const float* __restrict__ t,
                       const float* __restrict__ W_time,
                       const float* __restrict__ b_time) {
    int idx = blockIdx.x * blockDim.x + threadIdx.x;
    if (idx < GG * SS) {
        int g = idx / SS, c = idx - g * SS;
        g_temb[idx] = fmaf(t[g], W_time[c], b_time[c]);
    }
    if (idx < GG * 3) g_sum[idx] = 0.f;
    if (idx < GG)     g_cnt[idx] = 0.f;
    if (idx < SS)     g_zbias[idx] = 0.f;
}

// ============================================================
// K1: per-graph position sums
// ============================================================
__global__ void k_possum(const float* __restrict__ pos,
                         const int* __restrict__ batch) {
    int n = blockIdx.x * blockDim.x + threadIdx.x;
    if (n >= NN) return;
    int b = batch[n];
    atomicAdd(&g_sum[b * 3 + 0], pos[n * 3 + 0]);
    atomicAdd(&g_sum[b * 3 + 1], pos[n * 3 + 1]);
    atomicAdd(&g_sum[b * 3 + 2], pos[n * 3 + 2]);
    atomicAdd(&g_cnt[b], 1.0f);
}

// ============================================================
// K2: center positions; emit coords_pred and coords_eps0
// ============================================================
__global__ void k_center(const float* __restrict__ pos,
                         const int* __restrict__ batch,
                         float* __restrict__ out) {
    int n = blockIdx.x * blockDim.x + threadIdx.x;
    if (n >= NN) return;
    int b = batch[n];
    float inv = 1.0f / fmaxf(g_cnt[b], 1.0f);
#pragma unroll
    for (int k = 0; k < 3; k++) {
        float v = pos[n * 3 + k] - g_sum[b * 3 + k] * inv;
        g_posc[n * 3 + k] = v;
        out[OFF_CP + n * 3 + k] = v;
        out[OFF_CE0 + n * 3 + k] = 0.f;
    }
}

// ============================================================
// K3: h1 = x @ W_atom + b_atom + temb[batch]   (block per node)
// ============================================================
__global__ void k_nodein(const float* __restrict__ x,
                         const float* __restrict__ W_atom,
                         const float* __restrict__ b_atom,
                         const int* __restrict__ batch) {
    int n = blockIdx.x;
    int c = threadIdx.x;
    __shared__ float xs[NAn];
    __shared__ int bsh;
    if (c < NAn) xs[c] = x[n * NAn + c];
    if (c == 0) bsh = batch[n];
    __syncthreads();
    float acc = b_atom[c] + g_temb[bsh * SS + c];
#pragma unroll
    for (int k = 0; k < NAn; k++) acc = fmaf(xs[k], W_atom[k * SS + c], acc);
    g_bufA[n * SS + c] = acc;
}

// ============================================================
// Generic fp32 GEMM  C[N,256] = act(A[N,256] @ W[256,256] + bias)
// ============================================================
#define BM 64
#define BN 64
#define BKc 16
template <int ACT>
__global__ void __launch_bounds__(256) k_gemm(const float* __restrict__ A,
                                              const float* __restrict__ W,
                                              const float* __restrict__ bias,
                                              float* __restrict__ C) {
    __shared__ float As[BKc][BM + 1];
    __shared__ float Bs[BKc][BN];
    int tid = threadIdx.x;
    int row0 = blockIdx.y * BM;
    int col0 = blockIdx.x * BN;
    int ar = tid >> 2;
    int ak = (tid & 3) << 2;
    int bk = tid >> 4;
    int bc = (tid & 15) << 2;
    int ty = tid >> 4;
    int tx = tid & 15;
    float acc[4][4] = {};
    for (int k0 = 0; k0 < SS; k0 += BKc) {
        float4 av = make_float4(0.f, 0.f, 0.f, 0.f);
        if (row0 + ar < NN)
            av = *(const float4*)&A[(size_t)(row0 + ar) * SS + k0 + ak];
        As[ak + 0][ar] = av.x;
        As[ak + 1][ar] = av.y;
        As[ak + 2][ar] = av.z;
        As[ak + 3][ar] = av.w;
        *(float4*)&Bs[bk][bc] = *(const float4*)&W[(size_t)(k0 + bk) * SS + col0 + bc];
        __syncthreads();
#pragma unroll
        for (int k = 0; k < BKc; k++) {
            float a0 = As[k][ty * 4 + 0];
            float a1 = As[k][ty * 4 + 1];
            float a2 = As[k][ty * 4 + 2];
            float a3 = As[k][ty * 4 + 3];
            float4 bv = *(const float4*)&Bs[k][tx * 4];
            acc[0][0] = fmaf(a0, bv.x, acc[0][0]); acc[0][1] = fmaf(a0, bv.y, acc[0][1]);
            acc[0][2] = fmaf(a0, bv.z, acc[0][2]); acc[0][3] = fmaf(a0, bv.w, acc[0][3]);
            acc[1][0] = fmaf(a1, bv.x, acc[1][0]); acc[1][1] = fmaf(a1, bv.y, acc[1][1]);
            acc[1][2] = fmaf(a1, bv.z, acc[1][2]); acc[1][3] = fmaf(a1, bv.w, acc[1][3]);
            acc[2][0] = fmaf(a2, bv.x, acc[2][0]); acc[2][1] = fmaf(a2, bv.y, acc[2][1]);
            acc[2][2] = fmaf(a2, bv.z, acc[2][2]); acc[2][3] = fmaf(a2, bv.w, acc[2][3]);
            acc[3][0] = fmaf(a3, bv.x, acc[3][0]); acc[3][1] = fmaf(a3, bv.y, acc[3][1]);
            acc[3][2] = fmaf(a3, bv.z, acc[3][2]); acc[3][3] = fmaf(a3, bv.w, acc[3][3]);
        }
        __syncthreads();
    }
#pragma unroll
    for (int i2 = 0; i2 < 4; i2++) {
        int row = row0 + ty * 4 + i2;
        if (row >= NN) continue;
#pragma unroll
        for (int j2 = 0; j2 < 4; j2++) {
            int col = col0 + tx * 4 + j2;
            float v = acc[i2][j2] + bias[col];
            if (ACT == 1) v = v / (1.0f + expf(-v));
            C[(size_t)row * SS + col] = v;
        }
    }
}

// ============================================================
// K7: atoms = h3 @ W_atoms + b_atoms  (warp per node; lane = out col)
// ============================================================
__global__ void k_atoms(const float* __restrict__ h3,
                        const float* __restrict__ W_atoms,
                        const float* __restrict__ b_atoms,
                        float* __restrict__ out) {
    int w = (blockIdx.x * blockDim.x + threadIdx.x) >> 5;
    int lane = threadIdx.x & 31;
    if (w >= NN) return;
    float acc = b_atoms[lane];
    for (int k0 = 0; k0 < SS; k0 += 32) {
        float hv = h3[w * SS + k0 + lane];
#pragma unroll
        for (int kk = 0; kk < 32; kk++) {
            float h = __shfl_sync(0xffffffffu, hv, kk);
            acc = fmaf(h, W_atoms[(k0 + kk) * 32 + lane], acc);
        }
    }
    if (lane < NAn) out[OFF_AE + w * NAn + lane] = acc;
    else            out[OFF_AP + w * NAn + (lane - NAn)] = acc;
}

// ============================================================
// K8: local edge attrs d_l, rn_l
// ============================================================
__global__ void k_local(const int* __restrict__ eil, float* __restrict__ out) {
    int e = blockIdx.x * blockDim.x + threadIdx.x;
    if (e >= ELn) return;
    int s = eil[e];
    int tg = eil[ELn + e];
    float rx = g_posc[tg * 3 + 0] - g_posc[s * 3 + 0];
    float ry = g_posc[tg * 3 + 1] - g_posc[s * 3 + 1];
    float rz = g_posc[tg * 3 + 2] - g_posc[s * 3 + 2];
    float ss = rx * rx + ry * ry + rz * rz;
    float d = sqrtf(fmaxf(ss, 1e-6f));
    out[OFF_DL + e] = d;
    float inv = 1.0f / d;
    out[OFF_RNL + 3 * e + 0] = rx * inv;
    out[OFF_RNL + 3 * e + 1] = ry * inv;
    out[OFF_RNL + 3 * e + 2] = rz * inv;
}

// ============================================================
// K9: global edges — fused edge attrs + bonds MLP
// ============================================================
__global__ void __launch_bounds__(256) k_global(const int* __restrict__ eig,
                                                const float* __restrict__ u,
                                                const float* __restrict__ W_b0,
                                                const float* __restrict__ b_b0,
                                                const float* __restrict__ W_b1,
                                                const float* __restrict__ b_b1,
                                                float* __restrict__ out) {
    int lane = threadIdx.x & 31;
    int warp0 = (blockIdx.x * blockDim.x + threadIdx.x) >> 5;
    int nwarps = (gridDim.x * blockDim.x) >> 5;
    int ch0 = lane * 8;

    float wb1[8][10];
    float wd[8], bb[8];
#pragma unroll
    for (int k = 0; k < 8; k++) {
        wd[k] = W_b0[SS * SS + ch0 + k];   // row index S of (S+1,S) weight
        bb[k] = b_b0[ch0 + k];
#pragma unroll
        for (int o = 0; o < 10; o++) wb1[k][o] = W_b1[(ch0 + k) * 10 + o];
    }
    float bb1 = (lane < 10) ? b_b1[lane] : 0.f;

    for (int e = warp0; e < EGn; e += nwarps) {
        int j = eig[e];          // src
        int i = eig[EGn + e];    // tgt
        float pix = g_posc[i * 3 + 0], piy = g_posc[i * 3 + 1], piz = g_posc[i * 3 + 2];
        float pjx = g_posc[j * 3 + 0], pjy = g_posc[j * 3 + 1], pjz = g_posc[j * 3 + 2];
        float rx = pix - pjx, ry = piy - pjy, rz = piz - pjz;
        float ss = rx * rx + ry * ry + rz * rz;
        float db = sqrtf(ss);                  // bonds distance (unclipped)
        float dc = sqrtf(fmaxf(ss, 1e-6f));    // clipped for r_norm
        if (lane == 0) {
            out[OFF_AG + e] = pix * pjx + piy * pjy + piz * pjz;
            float inv = 1.0f / dc;
            out[OFF_RNG + 3 * e + 0] = rx * inv;
            out[OFF_RNG + 3 * e + 1] = ry * inv;
            out[OFF_RNG + 3 * e + 2] = rz * inv;
        }
        const float4* ui = (const float4*)(u + (size_t)i * SS + ch0);
        const float4* uj = (const float4*)(u + (size_t)j * SS + ch0);
        float4 a0 = __ldg(ui);     float4 a1 = __ldg(ui + 1);
        float4 c0 = __ldg(uj);     float4 c1 = __ldg(uj + 1);
        float h[8] = {a0.x + c0.x, a0.y + c0.y, a0.z + c0.z, a0.w + c0.w,
                      a1.x + c1.x, a1.y + c1.y, a1.z + c1.z, a1.w + c1.w};
        float acc[10] = {};
#pragma unroll
        for (int k = 0; k < 8; k++) {
            float hv = fmaf(db, wd[k], h[k] + bb[k]);
            float sg = 1.0f / (1.0f + __expf(-hv));
            hv *= sg;
#pragma unroll
            for (int o = 0; o < 10; o++) acc[o] = fmaf(hv, wb1[k][o], acc[o]);
        }
#pragma unroll
        for (int off = 16; off > 0; off >>= 1) {
#pragma unroll
            for (int o = 0; o < 10; o++)
                acc[o] += __shfl_xor_sync(0xffffffffu, acc[o], off);
        }
        if (lane < 5)       out[OFF_BP + (size_t)e * 5 + lane] = acc[lane] + bb1;
        else if (lane < 10) out[OFF_BE + (size_t)e * 5 + (lane - 5)] = acc[lane] + bb1;
    }
}

// ============================================================
// Host launcher
// ============================================================
extern "C" void kernel_launch(void* const* d_in, const int* in_sizes, int n_in,
                              void* d_out, int out_size) {
    // Detect input ordering. Reference-signature order has edge_attr_global
    // (2,500,000 elems) at index 3; setup-dict order has edge_index_local
    // (320,000 elems) there.
    int iX, iT, iPOS, iWT, iBT, iWA, iBA, iWAT, iBAT, iWSH, iBSH,
        iWB0, iBB0, iWB1, iBB1, iWATM, iBATM, iEIL, iEIG, iBATCH;
    if (in_sizes[3] == 2 * ELn) {
        // setup-dict order: x,t,pos,eil,eig,eag,batch,W_time,b_time,W_atom,b_atom,
        //                   W_at,b_at,W_shared,b_shared,W_b0,b_b0,W_b1,b_b1,
        //                   W_coord,W_atoms,b_atoms
        iX = 0; iT = 1; iPOS = 2; iEIL = 3; iEIG = 4; iBATCH = 6;
        iWT = 7; iBT = 8; iWA = 9; iBA = 10; iWAT = 11; iBAT = 12;
        iWSH = 13; iBSH = 14; iWB0 = 15; iBB0 = 16; iWB1 = 17; iBB1 = 18;
        iWATM = 20; iBATM = 21;
    } else {
        // reference-signature order: x,t,pos,edge_attr_global,W_time,b_time,W_atom,
        //   b_atom,W_at,b_at,W_shared,b_shared,W_b0,b_b0,W_b1,b_b1,W_coord,
        //   W_atoms,b_atoms,eil,eig,batch
        iX = 0; iT = 1; iPOS = 2; iWT = 4; iBT = 5; iWA = 6; iBA = 7;
        iWAT = 8; iBAT = 9; iWSH = 10; iBSH = 11; iWB0 = 12; iBB0 = 13;
        iWB1 = 14; iBB1 = 15; iWATM = 17; iBATM = 18;
        iEIL = 19; iEIG = 20; iBATCH = 21;
    }

    const float* x       = (const float*)d_in[iX];
    const float* t       = (const float*)d_in[iT];
    const float* pos     = (const float*)d_in[iPOS];
    const float* W_time  = (const float*)d_in[iWT];
    const float* b_time  = (const float*)d_in[iBT];
    const float* W_atom  = (const float*)d_in[iWA];
    const float* b_atom  = (const float*)d_in[iBA];
    const float* W_at    = (const float*)d_in[iWAT];
    const float* b_at    = (const float*)d_in[iBAT];
    const float* W_sh    = (const float*)d_in[iWSH];
    const float* b_sh    = (const float*)d_in[iBSH];
    const float* W_b0    = (const float*)d_in[iWB0];
    const float* b_b0    = (const float*)d_in[iBB0];
    const float* W_b1    = (const float*)d_in[iWB1];
    const float* b_b1    = (const float*)d_in[iBB1];
    const float* W_atoms = (const float*)d_in[iWATM];
    const float* b_atoms = (const float*)d_in[iBATM];
    const int* eil       = (const int*)d_in[iEIL];
    const int* eig       = (const int*)d_in[iEIG];
    const int* batch     = (const int*)d_in[iBATCH];
    float* out = (float*)d_out;

    float *bufA, *bufB, *zbias;
    cudaGetSymbolAddress((void**)&bufA, g_bufA);
    cudaGetSymbolAddress((void**)&bufB, g_bufB);
    cudaGetSymbolAddress((void**)&zbias, g_zbias);

    k_init<<<(GG * SS + 255) / 256, 256>>>(t, W_time, b_time);
    k_possum<<<(NN + 255) / 256, 256>>>(pos, batch);
    k_center<<<(NN + 255) / 256, 256>>>(pos, batch, out);
    k_nodein<<<NN, SS>>>(x, W_atom, b_atom, batch);

    dim3 gg(SS / BN, (NN + BM - 1) / BM);
    k_gemm<0><<<gg, 256>>>(bufA, W_at, b_at, bufB);     // h2
    k_gemm<1><<<gg, 256>>>(bufB, W_sh, b_sh, bufA);     // h3 = silu(...)
    k_gemm<0><<<gg, 256>>>(bufA, W_b0, zbias, bufB);    // u (bias-free; b_b0 added per-edge)

    k_atoms<<<(NN * 32 + 255) / 256, 256>>>(bufA, W_atoms, b_atoms, out);
    k_local<<<(ELn + 255) / 256, 256>>>(eil, out);
    k_global<<<1184, 256>>>(eig, bufB, W_b0, b_b0, W_b1, b_b1, out);
}

// round 4
// speedup vs baseline: 1.0216x; 1.0216x over previous
#include <cuda_runtime.h>
#include <math.h>

#define NN   10000
#define GG   200
#define ELn  160000
#define EGn  500000
#define SS   256
#define NAn  16
#define NBn  5

// ---- output offsets (floats) ----
#define OFF_CP   0           // coords_pred  (N,3)
#define OFF_CE0  30000       // coords_eps0  (N,3)
#define OFF_AP   60000       // atoms_pred   (N,16)
#define OFF_AE   220000      // atoms_eps    (N,16)
#define OFF_BP   380000      // bonds_pred   (EG,5)
#define OFF_BE   2880000     // bonds_eps    (EG,5)
#define OFF_DL   5380000     // d_l          (EL,)
#define OFF_RNL  5540000     // rn_l         (EL,3)
#define OFF_AG   6020000     // a_g          (EG,)
#define OFF_RNG  6520000     // rn_g         (EG,3)

// ---- scratch (device globals; no allocation allowed) ----
__device__ float g_sum[GG * 3];
__device__ float g_cnt[GG];
__device__ float g_temb2[GG * SS];   // (temb + b_atom) @ W_at + b_at
__device__ float g_Wc[NAn * SS];     // W_atom @ W_at
__device__ float g_posc[NN * 3];
__device__ float g_bufA[NN * SS];
__device__ float g_bufB[NN * SS];

// ============================================================
// K0: zero per-graph accumulators
// ============================================================
__global__ void k_zero() {
    int idx = blockIdx.x * blockDim.x + threadIdx.x;
    if (idx < GG * 3) g_sum[idx] = 0.f;
    if (idx < GG)     g_cnt[idx] = 0.f;
}

// ============================================================
// K_temb2: temb2[g] = (t[g]*W_time + b_time + b_atom) @ W_at + b_at
// block per graph, thread per output column
// ============================================================
__global__ void __launch_bounds__(256) k_temb2(const float* __restrict__ t,
                                               const float* __restrict__ W_time,
                                               const float* __restrict__ b_time,
                                               const float* __restrict__ b_atom,
                                               const float* __restrict__ W_at,
                                               const float* __restrict__ b_at) {
    int g = blockIdx.x;
    int c = threadIdx.x;
    __shared__ float tin[SS];
    tin[c] = fmaf(t[g], W_time[c], b_time[c]) + b_atom[c];
    __syncthreads();
    float a0 = 0.f, a1 = 0.f, a2 = 0.f, a3 = 0.f;
#pragma unroll 4
    for (int k = 0; k < SS; k += 4) {
        a0 = fmaf(tin[k + 0], W_at[(k + 0) * SS + c], a0);
        a1 = fmaf(tin[k + 1], W_at[(k + 1) * SS + c], a1);
        a2 = fmaf(tin[k + 2], W_at[(k + 2) * SS + c], a2);
        a3 = fmaf(tin[k + 3], W_at[(k + 3) * SS + c], a3);
    }
    g_temb2[g * SS + c] = (a0 + a1) + (a2 + a3) + b_at[c];
}

// ============================================================
// K_wc: Wc = W_atom(16x256) @ W_at(256x256)  -> (16,256)
// ============================================================
__global__ void __launch_bounds__(256) k_wc(const float* __restrict__ W_atom,
                                            const float* __restrict__ W_at) {
    int r = blockIdx.x;
    int c = threadIdx.x;
    __shared__ float arow[SS];
    arow[c] = W_atom[r * SS + c];
    __syncthreads();
    float a0 = 0.f, a1 = 0.f, a2 = 0.f, a3 = 0.f;
#pragma unroll 4
    for (int k = 0; k < SS; k += 4) {
        a0 = fmaf(arow[k + 0], W_at[(k + 0) * SS + c], a0);
        a1 = fmaf(arow[k + 1], W_at[(k + 1) * SS + c], a1);
        a2 = fmaf(arow[k + 2], W_at[(k + 2) * SS + c], a2);
        a3 = fmaf(arow[k + 3], W_at[(k + 3) * SS + c], a3);
    }
    g_Wc[r * SS + c] = (a0 + a1) + (a2 + a3);
}

// ============================================================
// K1: per-graph position sums
// ============================================================
__global__ void k_possum(const float* __restrict__ pos,
                         const int* __restrict__ batch) {
    int n = blockIdx.x * blockDim.x + threadIdx.x;
    if (n >= NN) return;
    int b = batch[n];
    atomicAdd(&g_sum[b * 3 + 0], pos[n * 3 + 0]);
    atomicAdd(&g_sum[b * 3 + 1], pos[n * 3 + 1]);
    atomicAdd(&g_sum[b * 3 + 2], pos[n * 3 + 2]);
    atomicAdd(&g_cnt[b], 1.0f);
}

// ============================================================
// K2: center positions; emit coords_pred and coords_eps0
// ============================================================
__global__ void k_center(const float* __restrict__ pos,
                         const int* __restrict__ batch,
                         float* __restrict__ out) {
    int n = blockIdx.x * blockDim.x + threadIdx.x;
    if (n >= NN) return;
    int b = batch[n];
    float inv = 1.0f / fmaxf(g_cnt[b], 1.0f);
#pragma unroll
    for (int k = 0; k < 3; k++) {
        float v = pos[n * 3 + k] - g_sum[b * 3 + k] * inv;
        g_posc[n * 3 + k] = v;
        out[OFF_CP + n * 3 + k] = v;
        out[OFF_CE0 + n * 3 + k] = 0.f;
    }
}

// ============================================================
// K_h2: h2 = x @ Wc + temb2[batch]   (block per node; K=16 only)
// ============================================================
__global__ void __launch_bounds__(256) k_h2(const float* __restrict__ x,
                                            const int* __restrict__ batch) {
    int n = blockIdx.x;
    int c = threadIdx.x;
    __shared__ float xs[NAn];
    __shared__ int bsh;
    if (c < NAn) xs[c] = x[n * NAn + c];
    if (c == 0) bsh = batch[n];
    __syncthreads();
    float acc = g_temb2[bsh * SS + c];
#pragma unroll
    for (int k = 0; k < NAn; k++) acc = fmaf(xs[k], g_Wc[k * SS + c], acc);
    g_bufA[n * SS + c] = acc;
}

// ============================================================
// Fast fp32 GEMM  C[N,256] = act(A[N,256] @ W[256,256] + bias)
// 128x128 block tile, BK=8, 8x8 micro-tile, 256 threads.
// ACT: 0 = bias only, 1 = bias + silu, 2 = raw (no bias, no act)
// ============================================================
template <int ACT>
__global__ void __launch_bounds__(256) k_gemm128(const float* __restrict__ A,
                                                 const float* __restrict__ W,
                                                 const float* __restrict__ bias,
                                                 float* __restrict__ C) {
    __shared__ float As[8][132];
    __shared__ float Bs[8][128];
    const int tid = threadIdx.x;
    const int row0 = blockIdx.y * 128;
    const int col0 = blockIdx.x * 128;
    const int ar = tid >> 1;             // 0..127
    const int ak = (tid & 1) * 4;        // 0 or 4
    const int bk = tid >> 5;             // 0..7
    const int bc = (tid & 31) * 4;       // 0..124
    const int ty = tid >> 4;             // 0..15
    const int tx = tid & 15;             // 0..15

    float acc[8][8] = {};
    for (int k0 = 0; k0 < SS; k0 += 8) {
        float4 av = make_float4(0.f, 0.f, 0.f, 0.f);
        int arow = row0 + ar;
        if (arow < NN)
            av = *(const float4*)&A[(size_t)arow * SS + k0 + ak];
        As[ak + 0][ar] = av.x;
        As[ak + 1][ar] = av.y;
        As[ak + 2][ar] = av.z;
        As[ak + 3][ar] = av.w;
        *(float4*)&Bs[bk][bc] = *(const float4*)&W[(size_t)(k0 + bk) * SS + col0 + bc];
        __syncthreads();
#pragma unroll
        for (int k = 0; k < 8; k++) {
            float a[8], b[8];
            *(float4*)&a[0] = *(const float4*)&As[k][ty * 8];
            *(float4*)&a[4] = *(const float4*)&As[k][ty * 8 + 4];
            *(float4*)&b[0] = *(const float4*)&Bs[k][tx * 8];
            *(float4*)&b[4] = *(const float4*)&Bs[k][tx * 8 + 4];
#pragma unroll
            for (int i = 0; i < 8; i++)
#pragma unroll
                for (int j = 0; j < 8; j++)
                    acc[i][j] = fmaf(a[i], b[j], acc[i][j]);
        }
        __syncthreads();
    }
#pragma unroll
    for (int i = 0; i < 8; i++) {
        int row = row0 + ty * 8 + i;
        if (row >= NN) continue;
#pragma unroll
        for (int j = 0; j < 8; j += 4) {
            int col = col0 + tx * 8 + j;
            float4 v;
            v.x = acc[i][j + 0];
            v.y = acc[i][j + 1];
            v.z = acc[i][j + 2];
            v.w = acc[i][j + 3];
            if (ACT != 2) {
                v.x += bias[col + 0];
                v.y += bias[col + 1];
                v.z += bias[col + 2];
                v.w += bias[col + 3];
            }
            if (ACT == 1) {
                v.x = v.x / (1.0f + __expf(-v.x));
                v.y = v.y / (1.0f + __expf(-v.y));
                v.z = v.z / (1.0f + __expf(-v.z));
                v.w = v.w / (1.0f + __expf(-v.w));
            }
            *(float4*)&C[(size_t)row * SS + col] = v;
        }
    }
}

// ============================================================
// K7: atoms = h3 @ W_atoms + b_atoms  (warp per node; lane = out col)
// ============================================================
__global__ void k_atoms(const float* __restrict__ h3,
                        const float* __restrict__ W_atoms,
                        const float* __restrict__ b_atoms,
                        float* __restrict__ out) {
    int w = (blockIdx.x * blockDim.x + threadIdx.x) >> 5;
    int lane = threadIdx.x & 31;
    if (w >= NN) return;
    float acc = b_atoms[lane];
    for (int k0 = 0; k0 < SS; k0 += 32) {
        float hv = h3[w * SS + k0 + lane];
#pragma unroll
        for (int kk = 0; kk < 32; kk++) {
            float h = __shfl_sync(0xffffffffu, hv, kk);
            acc = fmaf(h, W_atoms[(k0 + kk) * 32 + lane], acc);
        }
    }
    if (lane < NAn) out[OFF_AE + w * NAn + lane] = acc;
    else            out[OFF_AP + w * NAn + (lane - NAn)] = acc;
}

// ============================================================
// K8: local edge attrs d_l, rn_l
// ============================================================
__global__ void k_local(const int* __restrict__ eil, float* __restrict__ out) {
    int e = blockIdx.x * blockDim.x + threadIdx.x;
    if (e >= ELn) return;
    int s = eil[e];
    int tg = eil[ELn + e];
    float rx = g_posc[tg * 3 + 0] - g_posc[s * 3 + 0];
    float ry = g_posc[tg * 3 + 1] - g_posc[s * 3 + 1];
    float rz = g_posc[tg * 3 + 2] - g_posc[s * 3 + 2];
    float ss = rx * rx + ry * ry + rz * rz;
    float d = sqrtf(fmaxf(ss, 1e-6f));
    out[OFF_DL + e] = d;
    float inv = 1.0f / d;
    out[OFF_RNL + 3 * e + 0] = rx * inv;
    out[OFF_RNL + 3 * e + 1] = ry * inv;
    out[OFF_RNL + 3 * e + 2] = rz * inv;
}

// ============================================================
// K9: global edges — fused edge attrs + bonds MLP
// ============================================================
__global__ void __launch_bounds__(256) k_global(const int* __restrict__ eig,
                                                const float* __restrict__ u,
                                                const float* __restrict__ W_b0,
                                                const float* __restrict__ b_b0,
                                                const float* __restrict__ W_b1,
                                                const float* __restrict__ b_b1,
                                                float* __restrict__ out) {
    int lane = threadIdx.x & 31;
    int warp0 = (blockIdx.x * blockDim.x + threadIdx.x) >> 5;
    int nwarps = (gridDim.x * blockDim.x) >> 5;
    int ch0 = lane * 8;

    float wb1[8][10];
    float wd[8], bb[8];
#pragma unroll
    for (int k = 0; k < 8; k++) {
        wd[k] = W_b0[SS * SS + ch0 + k];   // row index S of (S+1,S) weight
        bb[k] = b_b0[ch0 + k];
#pragma unroll
        for (int o = 0; o < 10; o++) wb1[k][o] = W_b1[(ch0 + k) * 10 + o];
    }
    float bb1 = (lane < 10) ? b_b1[lane] : 0.f;

    for (int e = warp0; e < EGn; e += nwarps) {
        int j = eig[e];          // src
        int i = eig[EGn + e];    // tgt
        float pix = g_posc[i * 3 + 0], piy = g_posc[i * 3 + 1], piz = g_posc[i * 3 + 2];
        float pjx = g_posc[j * 3 + 0], pjy = g_posc[j * 3 + 1], pjz = g_posc[j * 3 + 2];
        float rx = pix - pjx, ry = piy - pjy, rz = piz - pjz;
        float ss = rx * rx + ry * ry + rz * rz;
        float db = sqrtf(ss);                  // bonds distance (unclipped)
        float dc = sqrtf(fmaxf(ss, 1e-6f));    // clipped for r_norm
        if (lane == 0) {
            out[OFF_AG + e] = pix * pjx + piy * pjy + piz * pjz;
            float inv = 1.0f / dc;
            out[OFF_RNG + 3 * e + 0] = rx * inv;
            out[OFF_RNG + 3 * e + 1] = ry * inv;
            out[OFF_RNG + 3 * e + 2] = rz * inv;
        }
        const float4* ui = (const float4*)(u + (size_t)i * SS + ch0);
        const float4* uj = (const float4*)(u + (size_t)j * SS + ch0);
        float4 a0 = __ldg(ui);     float4 a1 = __ldg(ui + 1);
        float4 c0 = __ldg(uj);     float4 c1 = __ldg(uj + 1);
        float h[8] = {a0.x + c0.x, a0.y + c0.y, a0.z + c0.z, a0.w + c0.w,
                      a1.x + c1.x, a1.y + c1.y, a1.z + c1.z, a1.w + c1.w};
        float acc[10] = {};
#pragma unroll
        for (int k = 0; k < 8; k++) {
            float hv = fmaf(db, wd[k], h[k] + bb[k]);
            float sg = 1.0f / (1.0f + __expf(-hv));
            hv *= sg;
#pragma unroll
            for (int o = 0; o < 10; o++) acc[o] = fmaf(hv, wb1[k][o], acc[o]);
        }
#pragma unroll
        for (int off = 16; off > 0; off >>= 1) {
#pragma unroll
            for (int o = 0; o < 10; o++)
                acc[o] += __shfl_xor_sync(0xffffffffu, acc[o], off);
        }
        if (lane < 5)       out[OFF_BP + (size_t)e * 5 + lane] = acc[lane] + bb1;
        else if (lane < 10) out[OFF_BE + (size_t)e * 5 + (lane - 5)] = acc[lane] + bb1;
    }
}

// ============================================================
// Host launcher
// ============================================================
extern "C" void kernel_launch(void* const* d_in, const int* in_sizes, int n_in,
                              void* d_out, int out_size) {
    int iX, iT, iPOS, iWT, iBT, iWA, iBA, iWAT, iBAT, iWSH, iBSH,
        iWB0, iBB0, iWB1, iBB1, iWATM, iBATM, iEIL, iEIG, iBATCH;
    if (in_sizes[3] == 2 * ELn) {
        // setup-dict order
        iX = 0; iT = 1; iPOS = 2; iEIL = 3; iEIG = 4; iBATCH = 6;
        iWT = 7; iBT = 8; iWA = 9; iBA = 10; iWAT = 11; iBAT = 12;
        iWSH = 13; iBSH = 14; iWB0 = 15; iBB0 = 16; iWB1 = 17; iBB1 = 18;
        iWATM = 20; iBATM = 21;
    } else {
        // reference-signature order
        iX = 0; iT = 1; iPOS = 2; iWT = 4; iBT = 5; iWA = 6; iBA = 7;
        iWAT = 8; iBAT = 9; iWSH = 10; iBSH = 11; iWB0 = 12; iBB0 = 13;
        iWB1 = 14; iBB1 = 15; iWATM = 17; iBATM = 18;
        iEIL = 19; iEIG = 20; iBATCH = 21;
    }

    const float* x       = (const float*)d_in[iX];
    const float* t       = (const float*)d_in[iT];
    const float* pos     = (const float*)d_in[iPOS];
    const float* W_time  = (const float*)d_in[iWT];
    const float* b_time  = (const float*)d_in[iBT];
    const float* W_atom  = (const float*)d_in[iWA];
    const float* b_atom  = (const float*)d_in[iBA];
    const float* W_at    = (const float*)d_in[iWAT];
    const float* b_at    = (const float*)d_in[iBAT];
    const float* W_sh    = (const float*)d_in[iWSH];
    const float* b_sh    = (const float*)d_in[iBSH];
    const float* W_b0    = (const float*)d_in[iWB0];
    const float* b_b0    = (const float*)d_in[iBB0];
    const float* W_b1    = (const float*)d_in[iWB1];
    const float* b_b1    = (const float*)d_in[iBB1];
    const float* W_atoms = (const float*)d_in[iWATM];
    const float* b_atoms = (const float*)d_in[iBATM];
    const int* eil       = (const int*)d_in[iEIL];
    const int* eig       = (const int*)d_in[iEIG];
    const int* batch     = (const int*)d_in[iBATCH];
    float* out = (float*)d_out;

    float *bufA, *bufB;
    cudaGetSymbolAddress((void**)&bufA, g_bufA);
    cudaGetSymbolAddress((void**)&bufB, g_bufB);

    k_zero<<<1, 1024>>>();
    k_temb2<<<GG, 256>>>(t, W_time, b_time, b_atom, W_at, b_at);
    k_wc<<<NAn, 256>>>(W_atom, W_at);
    k_possum<<<(NN + 255) / 256, 256>>>(pos, batch);
    k_center<<<(NN + 255) / 256, 256>>>(pos, batch, out);
    k_h2<<<NN, 256>>>(x, batch);                          // h2 -> bufA

    dim3 gg(SS / 128, (NN + 127) / 128);                  // (2, 79)
    k_gemm128<1><<<gg, 256>>>(bufA, W_sh, b_sh, bufB);    // h3 = silu(h2@W_sh+b) -> bufB
    k_gemm128<2><<<gg, 256>>>(bufB, W_b0, nullptr, bufA); // u = h3 @ W_b0[:256]  -> bufA

    k_atoms<<<(NN * 32 + 255) / 256, 256>>>(bufB, W_atoms, b_atoms, out);
    k_local<<<(ELn + 255) / 256, 256>>>(eil, out);
    k_global<<<1184, 256>>>(eig, bufA, W_b0, b_b0, W_b1, b_b1, out);
}

// round 5
// speedup vs baseline: 1.7518x; 1.7149x over previous
#include <cuda_runtime.h>
#include <math.h>

#define NN   10000
#define GG   200
#define ELn  160000
#define EGn  500000
#define SS   256
#define NAn  16
#define NBn  5

// ---- output offsets (floats) ----
#define OFF_CP   0
#define OFF_CE0  30000
#define OFF_AP   60000
#define OFF_AE   220000
#define OFF_BP   380000
#define OFF_BE   2880000
#define OFF_DL   5380000
#define OFF_RNL  5540000
#define OFF_AG   6020000
#define OFF_RNG  6520000

// ---- scratch ----
__device__ float g_sum[GG * 3];
__device__ float g_cnt[GG];
__device__ float g_temb2[GG * SS];
__device__ float g_Wc[NAn * SS];
__device__ float g_posc[NN * 3];
__device__ float g_bufA[NN * SS];
__device__ float g_bufB[NN * SS];

// ============================================================
// Launch 1 — k_pre (fused): temb2 (blocks 0..199), Wc (200..215),
//                           zero accumulators (block 216)
// ============================================================
__global__ void __launch_bounds__(256) k_pre(const float* __restrict__ t,
                                             const float* __restrict__ W_time,
                                             const float* __restrict__ b_time,
                                             const float* __restrict__ b_atom,
                                             const float* __restrict__ W_at,
                                             const float* __restrict__ b_at,
                                             const float* __restrict__ W_atom) {
    int b = blockIdx.x;
    int c = threadIdx.x;
    if (b < GG) {
        __shared__ float tin[SS];
        tin[c] = fmaf(t[b], W_time[c], b_time[c]) + b_atom[c];
        __syncthreads();
        float a0 = 0.f, a1 = 0.f, a2 = 0.f, a3 = 0.f;
#pragma unroll 4
        for (int k = 0; k < SS; k += 4) {
            a0 = fmaf(tin[k + 0], W_at[(k + 0) * SS + c], a0);
            a1 = fmaf(tin[k + 1], W_at[(k + 1) * SS + c], a1);
            a2 = fmaf(tin[k + 2], W_at[(k + 2) * SS + c], a2);
            a3 = fmaf(tin[k + 3], W_at[(k + 3) * SS + c], a3);
        }
        g_temb2[b * SS + c] = (a0 + a1) + (a2 + a3) + b_at[c];
    } else if (b < GG + NAn) {
        int r = b - GG;
        __shared__ float arow[SS];
        arow[c] = W_atom[r * SS + c];
        __syncthreads();
        float a0 = 0.f, a1 = 0.f, a2 = 0.f, a3 = 0.f;
#pragma unroll 4
        for (int k = 0; k < SS; k += 4) {
            a0 = fmaf(arow[k + 0], W_at[(k + 0) * SS + c], a0);
            a1 = fmaf(arow[k + 1], W_at[(k + 1) * SS + c], a1);
            a2 = fmaf(arow[k + 2], W_at[(k + 2) * SS + c], a2);
            a3 = fmaf(arow[k + 3], W_at[(k + 3) * SS + c], a3);
        }
        g_Wc[r * SS + c] = (a0 + a1) + (a2 + a3);
    } else {
        for (int i = c; i < GG * 3; i += 256) g_sum[i] = 0.f;
        for (int i = c; i < GG; i += 256)     g_cnt[i] = 0.f;
    }
}

// ============================================================
// Launch 2 — k_possum
// ============================================================
__global__ void k_possum(const float* __restrict__ pos,
                         const int* __restrict__ batch) {
    int n = blockIdx.x * blockDim.x + threadIdx.x;
    if (n >= NN) return;
    int b = batch[n];
    atomicAdd(&g_sum[b * 3 + 0], pos[n * 3 + 0]);
    atomicAdd(&g_sum[b * 3 + 1], pos[n * 3 + 1]);
    atomicAdd(&g_sum[b * 3 + 2], pos[n * 3 + 2]);
    atomicAdd(&g_cnt[b], 1.0f);
}

// ============================================================
// Launch 3 — k_center_h2 (fused): blocks 0..39 center+coords outputs,
//                                 blocks 40..10039 h2 per node
// ============================================================
__global__ void __launch_bounds__(256) k_center_h2(const float* __restrict__ pos,
                                                   const int* __restrict__ batch,
                                                   const float* __restrict__ x,
                                                   float* __restrict__ out) {
    if (blockIdx.x < 40) {
        int n = blockIdx.x * 256 + threadIdx.x;
        if (n >= NN) return;
        int b = batch[n];
        float inv = 1.0f / fmaxf(g_cnt[b], 1.0f);
#pragma unroll
        for (int k = 0; k < 3; k++) {
            float v = pos[n * 3 + k] - g_sum[b * 3 + k] * inv;
            g_posc[n * 3 + k] = v;
            out[OFF_CP + n * 3 + k] = v;
            out[OFF_CE0 + n * 3 + k] = 0.f;
        }
    } else {
        int n = blockIdx.x - 40;
        int c = threadIdx.x;
        __shared__ float xs[NAn];
        __shared__ int bsh;
        if (c < NAn) xs[c] = x[n * NAn + c];
        if (c == 0) bsh = batch[n];
        __syncthreads();
        float acc = g_temb2[bsh * SS + c];
#pragma unroll
        for (int k = 0; k < NAn; k++) acc = fmaf(xs[k], g_Wc[k * SS + c], acc);
        g_bufA[n * SS + c] = acc;
    }
}

// ============================================================
// Launches 4,5 — fp32 GEMM  C[N,256] = act(A @ W + bias)
// 64x128 tile, BK=8, 4x8 micro, 256 threads. grid (2,157)=314 blocks.
// ACT: 1 = bias+silu, 2 = raw
// ============================================================
template <int ACT>
__global__ void __launch_bounds__(256) k_gemm64(const float* __restrict__ A,
                                                const float* __restrict__ W,
                                                const float* __restrict__ bias,
                                                float* __restrict__ C) {
    __shared__ float As[8][68];
    __shared__ float Bs[8][128];
    const int tid = threadIdx.x;
    const int row0 = blockIdx.y * 64;
    const int col0 = blockIdx.x * 128;
    const int ar = tid >> 2;            // 0..63
    const int ak = (tid & 3) * 2;       // 0,2,4,6
    const int bk = tid >> 5;            // 0..7
    const int bc = (tid & 31) * 4;      // 0..124
    const int ty = tid >> 4;            // 0..15 -> 4 rows each
    const int tx = tid & 15;            // 0..15 -> 8 cols each

    float acc[4][8] = {};
    for (int k0 = 0; k0 < SS; k0 += 8) {
        float2 av = make_float2(0.f, 0.f);
        int arow = row0 + ar;
        if (arow < NN)
            av = *(const float2*)&A[(size_t)arow * SS + k0 + ak];
        As[ak + 0][ar] = av.x;
        As[ak + 1][ar] = av.y;
        *(float4*)&Bs[bk][bc] = *(const float4*)&W[(size_t)(k0 + bk) * SS + col0 + bc];
        __syncthreads();
#pragma unroll
        for (int k = 0; k < 8; k++) {
            float a[4], b[8];
            *(float4*)&a[0] = *(const float4*)&As[k][ty * 4];
            *(float4*)&b[0] = *(const float4*)&Bs[k][tx * 8];
            *(float4*)&b[4] = *(const float4*)&Bs[k][tx * 8 + 4];
#pragma unroll
            for (int i = 0; i < 4; i++)
#pragma unroll
                for (int j = 0; j < 8; j++)
                    acc[i][j] = fmaf(a[i], b[j], acc[i][j]);
        }
        __syncthreads();
    }
#pragma unroll
    for (int i = 0; i < 4; i++) {
        int row = row0 + ty * 4 + i;
        if (row >= NN) continue;
#pragma unroll
        for (int j = 0; j < 8; j += 4) {
            int col = col0 + tx * 8 + j;
            float4 v;
            v.x = acc[i][j + 0];
            v.y = acc[i][j + 1];
            v.z = acc[i][j + 2];
            v.w = acc[i][j + 3];
            if (ACT != 2) {
                v.x += bias[col + 0];
                v.y += bias[col + 1];
                v.z += bias[col + 2];
                v.w += bias[col + 3];
            }
            if (ACT == 1) {
                v.x = __fdividef(v.x, 1.0f + __expf(-v.x));
                v.y = __fdividef(v.y, 1.0f + __expf(-v.y));
                v.z = __fdividef(v.z, 1.0f + __expf(-v.z));
                v.w = __fdividef(v.w, 1.0f + __expf(-v.w));
            }
            *(float4*)&C[(size_t)row * SS + col] = v;
        }
    }
}

// ============================================================
// Launch 6 — k_global: fused global-edge attrs + bonds MLP (NCU TARGET)
// ============================================================
__global__ void __launch_bounds__(256) k_global(const int* __restrict__ eig,
                                                const float* __restrict__ u,
                                                const float* __restrict__ W_b0,
                                                const float* __restrict__ b_b0,
                                                const float* __restrict__ W_b1,
                                                const float* __restrict__ b_b1,
                                                float* __restrict__ out) {
    int lane = threadIdx.x & 31;
    int warp0 = (blockIdx.x * blockDim.x + threadIdx.x) >> 5;
    int nwarps = (gridDim.x * blockDim.x) >> 5;
    int ch0 = lane * 8;

    float wb1[8][10];
    float wd[8], bb[8];
#pragma unroll
    for (int k = 0; k < 8; k++) {
        wd[k] = W_b0[SS * SS + ch0 + k];
        bb[k] = b_b0[ch0 + k];
#pragma unroll
        for (int o = 0; o < 10; o++) wb1[k][o] = W_b1[(ch0 + k) * 10 + o];
    }
    float bb1 = (lane < 10) ? b_b1[lane] : 0.f;

    for (int e = warp0; e < EGn; e += nwarps) {
        int j = eig[e];
        int i = eig[EGn + e];
        float pix = g_posc[i * 3 + 0], piy = g_posc[i * 3 + 1], piz = g_posc[i * 3 + 2];
        float pjx = g_posc[j * 3 + 0], pjy = g_posc[j * 3 + 1], pjz = g_posc[j * 3 + 2];
        float rx = pix - pjx, ry = piy - pjy, rz = piz - pjz;
        float ss = rx * rx + ry * ry + rz * rz;
        float db = sqrtf(ss);
        if (lane == 0) {
            out[OFF_AG + e] = pix * pjx + piy * pjy + piz * pjz;
            float inv = rsqrtf(fmaxf(ss, 1e-6f));
            out[OFF_RNG + 3 * e + 0] = rx * inv;
            out[OFF_RNG + 3 * e + 1] = ry * inv;
            out[OFF_RNG + 3 * e + 2] = rz * inv;
        }
        const float4* ui = (const float4*)(u + (size_t)i * SS + ch0);
        const float4* uj = (const float4*)(u + (size_t)j * SS + ch0);
        float4 a0 = __ldg(ui);     float4 a1 = __ldg(ui + 1);
        float4 c0 = __ldg(uj);     float4 c1 = __ldg(uj + 1);
        float h[8] = {a0.x + c0.x, a0.y + c0.y, a0.z + c0.z, a0.w + c0.w,
                      a1.x + c1.x, a1.y + c1.y, a1.z + c1.z, a1.w + c1.w};
        float acc[10] = {};
#pragma unroll
        for (int k = 0; k < 8; k++) {
            float pre = fmaf(db, wd[k], h[k] + bb[k]);
            float hv = __fdividef(pre, 1.0f + __expf(-pre));
#pragma unroll
            for (int o = 0; o < 10; o++) acc[o] = fmaf(hv, wb1[k][o], acc[o]);
        }
#pragma unroll
        for (int off = 16; off > 0; off >>= 1) {
#pragma unroll
            for (int o = 0; o < 10; o++)
                acc[o] += __shfl_xor_sync(0xffffffffu, acc[o], off);
        }
        if (lane < 5)       out[OFF_BP + (size_t)e * 5 + lane] = acc[lane] + bb1;
        else if (lane < 10) out[OFF_BE + (size_t)e * 5 + (lane - 5)] = acc[lane] + bb1;
    }
}

// ============================================================
// Launch 7 — k_atoms
// ============================================================
__global__ void k_atoms(const float* __restrict__ h3,
                        const float* __restrict__ W_atoms,
                        const float* __restrict__ b_atoms,
                        float* __restrict__ out) {
    int w = (blockIdx.x * blockDim.x + threadIdx.x) >> 5;
    int lane = threadIdx.x & 31;
    if (w >= NN) return;
    float acc = b_atoms[lane];
    for (int k0 = 0; k0 < SS; k0 += 32) {
        float hv = h3[w * SS + k0 + lane];
#pragma unroll
        for (int kk = 0; kk < 32; kk++) {
            float h = __shfl_sync(0xffffffffu, hv, kk);
            acc = fmaf(h, W_atoms[(k0 + kk) * 32 + lane], acc);
        }
    }
    if (lane < NAn) out[OFF_AE + w * NAn + lane] = acc;
    else            out[OFF_AP + w * NAn + (lane - NAn)] = acc;
}

// ============================================================
// Launch 8 — k_local
// ============================================================
__global__ void k_local(const int* __restrict__ eil, float* __restrict__ out) {
    int e = blockIdx.x * blockDim.x + threadIdx.x;
    if (e >= ELn) return;
    int s = eil[e];
    int tg = eil[ELn + e];
    float rx = g_posc[tg * 3 + 0] - g_posc[s * 3 + 0];
    float ry = g_posc[tg * 3 + 1] - g_posc[s * 3 + 1];
    float rz = g_posc[tg * 3 + 2] - g_posc[s * 3 + 2];
    float ss = rx * rx + ry * ry + rz * rz;
    float sc = fmaxf(ss, 1e-6f);
    float d = sqrtf(sc);
    out[OFF_DL + e] = d;
    float inv = rsqrtf(sc);
    out[OFF_RNL + 3 * e + 0] = rx * inv;
    out[OFF_RNL + 3 * e + 1] = ry * inv;
    out[OFF_RNL + 3 * e + 2] = rz * inv;
}

// ============================================================
// Host launcher
// ============================================================
extern "C" void kernel_launch(void* const* d_in, const int* in_sizes, int n_in,
                              void* d_out, int out_size) {
    int iX, iT, iPOS, iWT, iBT, iWA, iBA, iWAT, iBAT, iWSH, iBSH,
        iWB0, iBB0, iWB1, iBB1, iWATM, iBATM, iEIL, iEIG, iBATCH;
    if (in_sizes[3] == 2 * ELn) {
        iX = 0; iT = 1; iPOS = 2; iEIL = 3; iEIG = 4; iBATCH = 6;
        iWT = 7; iBT = 8; iWA = 9; iBA = 10; iWAT = 11; iBAT = 12;
        iWSH = 13; iBSH = 14; iWB0 = 15; iBB0 = 16; iWB1 = 17; iBB1 = 18;
        iWATM = 20; iBATM = 21;
    } else {
        iX = 0; iT = 1; iPOS = 2; iWT = 4; iBT = 5; iWA = 6; iBA = 7;
        iWAT = 8; iBAT = 9; iWSH = 10; iBSH = 11; iWB0 = 12; iBB0 = 13;
        iWB1 = 14; iBB1 = 15; iWATM = 17; iBATM = 18;
        iEIL = 19; iEIG = 20; iBATCH = 21;
    }

    const float* x       = (const float*)d_in[iX];
    const float* t       = (const float*)d_in[iT];
    const float* pos     = (const float*)d_in[iPOS];
    const float* W_time  = (const float*)d_in[iWT];
    const float* b_time  = (const float*)d_in[iBT];
    const float* W_atom  = (const float*)d_in[iWA];
    const float* b_atom  = (const float*)d_in[iBA];
    const float* W_at    = (const float*)d_in[iWAT];
    const float* b_at    = (const float*)d_in[iBAT];
    const float* W_sh    = (const float*)d_in[iWSH];
    const float* b_sh    = (const float*)d_in[iBSH];
    const float* W_b0    = (const float*)d_in[iWB0];
    const float* b_b0    = (const float*)d_in[iBB0];
    const float* W_b1    = (const float*)d_in[iWB1];
    const float* b_b1    = (const float*)d_in[iBB1];
    const float* W_atoms = (const float*)d_in[iWATM];
    const float* b_atoms = (const float*)d_in[iBATM];
    const int* eil       = (const int*)d_in[iEIL];
    const int* eig       = (const int*)d_in[iEIG];
    const int* batch     = (const int*)d_in[iBATCH];
    float* out = (float*)d_out;

    float *bufA, *bufB;
    cudaGetSymbolAddress((void**)&bufA, g_bufA);
    cudaGetSymbolAddress((void**)&bufB, g_bufB);

    // 1
    k_pre<<<GG + NAn + 1, 256>>>(t, W_time, b_time, b_atom, W_at, b_at, W_atom);
    // 2
    k_possum<<<(NN + 255) / 256, 256>>>(pos, batch);
    // 3
    k_center_h2<<<40 + NN, 256>>>(pos, batch, x, out);
    // 4,5
    dim3 gg(2, (NN + 63) / 64);   // (2, 157)
    k_gemm64<1><<<gg, 256>>>(bufA, W_sh, b_sh, bufB);      // h3 -> bufB
    k_gemm64<2><<<gg, 256>>>(bufB, W_b0, nullptr, bufA);   // u  -> bufA
    // 6  (NCU capture window)
    k_global<<<1184, 256>>>(eig, bufA, W_b0, b_b0, W_b1, b_b1, out);
    // 7
    k_atoms<<<(NN * 32 + 255) / 256, 256>>>(bufB, W_atoms, b_atoms, out);
    // 8
    k_local<<<(ELn + 255) / 256, 256>>>(eil, out);
}

// round 6
// speedup vs baseline: 1.7874x; 1.0203x over previous
#include <cuda_runtime.h>
#include <math.h>

#define NN   10000
#define GG   200
#define ELn  160000
#define EGn  500000
#define SS   256
#define NAn  16
#define NBn  5

// ---- output offsets (floats) ----
#define OFF_CP   0
#define OFF_CE0  30000
#define OFF_AP   60000
#define OFF_AE   220000
#define OFF_BP   380000
#define OFF_BE   2880000
#define OFF_DL   5380000
#define OFF_RNL  5540000
#define OFF_AG   6020000
#define OFF_RNG  6520000

// ---- tail kernel block partition ----
#define GBLK 1184                 // k_global blocks
#define ABLK 1250                 // k_atoms blocks (1250*8 = 10000 nodes)
#define LBLK 625                  // k_local blocks (625*256 = 160000 edges)
#define NW_G (GBLK * 8)           // global-edge warps

// ---- scratch ----
__device__ float g_sum[GG * 3];
__device__ float g_cnt[GG];
__device__ float g_temb2[GG * SS];
__device__ float g_Wc[NAn * SS];
__device__ float g_posc[NN * 3];
__device__ float g_bufA[NN * SS];
__device__ float g_bufB[NN * SS];

// ============================================================
// Launch 1 — k_pre (fused): temb2 / Wc / zero accumulators
// ============================================================
__global__ void __launch_bounds__(256) k_pre(const float* __restrict__ t,
                                             const float* __restrict__ W_time,
                                             const float* __restrict__ b_time,
                                             const float* __restrict__ b_atom,
                                             const float* __restrict__ W_at,
                                             const float* __restrict__ b_at,
                                             const float* __restrict__ W_atom) {
    int b = blockIdx.x;
    int c = threadIdx.x;
    if (b < GG) {
        __shared__ float tin[SS];
        tin[c] = fmaf(t[b], W_time[c], b_time[c]) + b_atom[c];
        __syncthreads();
        float a0 = 0.f, a1 = 0.f, a2 = 0.f, a3 = 0.f;
#pragma unroll 4
        for (int k = 0; k < SS; k += 4) {
            a0 = fmaf(tin[k + 0], W_at[(k + 0) * SS + c], a0);
            a1 = fmaf(tin[k + 1], W_at[(k + 1) * SS + c], a1);
            a2 = fmaf(tin[k + 2], W_at[(k + 2) * SS + c], a2);
            a3 = fmaf(tin[k + 3], W_at[(k + 3) * SS + c], a3);
        }
        g_temb2[b * SS + c] = (a0 + a1) + (a2 + a3) + b_at[c];
    } else if (b < GG + NAn) {
        int r = b - GG;
        __shared__ float arow[SS];
        arow[c] = W_atom[r * SS + c];
        __syncthreads();
        float a0 = 0.f, a1 = 0.f, a2 = 0.f, a3 = 0.f;
#pragma unroll 4
        for (int k = 0; k < SS; k += 4) {
            a0 = fmaf(arow[k + 0], W_at[(k + 0) * SS + c], a0);
            a1 = fmaf(arow[k + 1], W_at[(k + 1) * SS + c], a1);
            a2 = fmaf(arow[k + 2], W_at[(k + 2) * SS + c], a2);
            a3 = fmaf(arow[k + 3], W_at[(k + 3) * SS + c], a3);
        }
        g_Wc[r * SS + c] = (a0 + a1) + (a2 + a3);
    } else {
        for (int i = c; i < GG * 3; i += 256) g_sum[i] = 0.f;
        for (int i = c; i < GG; i += 256)     g_cnt[i] = 0.f;
    }
}

// ============================================================
// Launch 2 — k_possum
// ============================================================
__global__ void k_possum(const float* __restrict__ pos,
                         const int* __restrict__ batch) {
    int n = blockIdx.x * blockDim.x + threadIdx.x;
    if (n >= NN) return;
    int b = batch[n];
    atomicAdd(&g_sum[b * 3 + 0], pos[n * 3 + 0]);
    atomicAdd(&g_sum[b * 3 + 1], pos[n * 3 + 1]);
    atomicAdd(&g_sum[b * 3 + 2], pos[n * 3 + 2]);
    atomicAdd(&g_cnt[b], 1.0f);
}

// ============================================================
// Launch 3 — k_center_h2 (fused)
// ============================================================
__global__ void __launch_bounds__(256) k_center_h2(const float* __restrict__ pos,
                                                   const int* __restrict__ batch,
                                                   const float* __restrict__ x,
                                                   float* __restrict__ out) {
    if (blockIdx.x < 40) {
        int n = blockIdx.x * 256 + threadIdx.x;
        if (n >= NN) return;
        int b = batch[n];
        float inv = 1.0f / fmaxf(g_cnt[b], 1.0f);
#pragma unroll
        for (int k = 0; k < 3; k++) {
            float v = pos[n * 3 + k] - g_sum[b * 3 + k] * inv;
            g_posc[n * 3 + k] = v;
            out[OFF_CP + n * 3 + k] = v;
            out[OFF_CE0 + n * 3 + k] = 0.f;
        }
    } else {
        int n = blockIdx.x - 40;
        int c = threadIdx.x;
        __shared__ float xs[NAn];
        __shared__ int bsh;
        if (c < NAn) xs[c] = x[n * NAn + c];
        if (c == 0) bsh = batch[n];
        __syncthreads();
        float acc = g_temb2[bsh * SS + c];
#pragma unroll
        for (int k = 0; k < NAn; k++) acc = fmaf(xs[k], g_Wc[k * SS + c], acc);
        g_bufA[n * SS + c] = acc;
    }
}

// ============================================================
// Launches 4,5 — fp32 GEMM, 64x128 tile, BK=8, double-buffered,
// conflict-free B fragments (tx*4 and 64+tx*4).
// ACT: 1 = bias+silu, 2 = raw
// ============================================================
template <int ACT>
__global__ void __launch_bounds__(256) k_gemm64(const float* __restrict__ A,
                                                const float* __restrict__ W,
                                                const float* __restrict__ bias,
                                                float* __restrict__ C) {
    __shared__ float As[2][8][68];
    __shared__ float Bs[2][8][128];
    const int tid = threadIdx.x;
    const int row0 = blockIdx.y * 64;
    const int col0 = blockIdx.x * 128;
    const int ar = tid >> 2;            // 0..63
    const int ak = (tid & 3) * 2;       // 0,2,4,6
    const int bk = tid >> 5;            // 0..7
    const int bc = (tid & 31) * 4;      // 0..124
    const int ty = tid >> 4;            // 0..15 (4 rows)
    const int tx = tid & 15;            // 0..15 (8 cols, split 4+4)
    const int arow = row0 + ar;

    // prologue: tile k0=0 -> buf 0
    {
        float2 av = make_float2(0.f, 0.f);
        if (arow < NN) av = *(const float2*)&A[(size_t)arow * SS + ak];
        float4 bv = *(const float4*)&W[(size_t)bk * SS + col0 + bc];
        As[0][ak + 0][ar] = av.x;
        As[0][ak + 1][ar] = av.y;
        *(float4*)&Bs[0][bk][bc] = bv;
    }
    __syncthreads();

    float acc[4][8] = {};
    for (int k0 = 0; k0 < SS; k0 += 8) {
        const int buf = (k0 >> 3) & 1;
        const bool more = (k0 + 8 < SS);
        float2 nav = make_float2(0.f, 0.f);
        float4 nbv;
        if (more) {
            if (arow < NN) nav = *(const float2*)&A[(size_t)arow * SS + k0 + 8 + ak];
            nbv = *(const float4*)&W[(size_t)(k0 + 8 + bk) * SS + col0 + bc];
        }
#pragma unroll
        for (int k = 0; k < 8; k++) {
            float a[4], b[8];
            *(float4*)&a[0] = *(const float4*)&As[buf][k][ty * 4];
            *(float4*)&b[0] = *(const float4*)&Bs[buf][k][tx * 4];
            *(float4*)&b[4] = *(const float4*)&Bs[buf][k][64 + tx * 4];
#pragma unroll
            for (int i = 0; i < 4; i++)
#pragma unroll
                for (int j = 0; j < 8; j++)
                    acc[i][j] = fmaf(a[i], b[j], acc[i][j]);
        }
        if (more) {
            As[buf ^ 1][ak + 0][ar] = nav.x;
            As[buf ^ 1][ak + 1][ar] = nav.y;
            *(float4*)&Bs[buf ^ 1][bk][bc] = nbv;
            __syncthreads();
        }
    }

#pragma unroll
    for (int i = 0; i < 4; i++) {
        int row = row0 + ty * 4 + i;
        if (row >= NN) continue;
#pragma unroll
        for (int half = 0; half < 2; half++) {
            int col = col0 + half * 64 + tx * 4;
            float4 v;
            v.x = acc[i][half * 4 + 0];
            v.y = acc[i][half * 4 + 1];
            v.z = acc[i][half * 4 + 2];
            v.w = acc[i][half * 4 + 3];
            if (ACT != 2) {
                v.x += bias[col + 0];
                v.y += bias[col + 1];
                v.z += bias[col + 2];
                v.w += bias[col + 3];
            }
            if (ACT == 1) {
                v.x = __fdividef(v.x, 1.0f + __expf(-v.x));
                v.y = __fdividef(v.y, 1.0f + __expf(-v.y));
                v.z = __fdividef(v.z, 1.0f + __expf(-v.z));
                v.w = __fdividef(v.w, 1.0f + __expf(-v.w));
            }
            *(float4*)&C[(size_t)row * SS + col] = v;
        }
    }
}

// ============================================================
// Launch 6 — k_tail (fused): global edges + atoms + local edges
// ============================================================
__global__ void __launch_bounds__(256) k_tail(const int* __restrict__ eig,
                                              const float* __restrict__ u,
                                              const float* __restrict__ W_b0,
                                              const float* __restrict__ b_b0,
                                              const float* __restrict__ W_b1,
                                              const float* __restrict__ b_b1,
                                              const float* __restrict__ h3,
                                              const float* __restrict__ W_atoms,
                                              const float* __restrict__ b_atoms,
                                              const int* __restrict__ eil,
                                              float* __restrict__ out) {
    const int blk = blockIdx.x;
    const int tid = threadIdx.x;
    const int lane = tid & 31;

    if (blk < GBLK) {
        // ---------------- global edges: attrs + bonds MLP ----------------
        int warp0 = blk * 8 + (tid >> 5);
        int ch0 = lane * 8;

        float wb1[8][10];
        float wd[8], bb[8];
#pragma unroll
        for (int k = 0; k < 8; k++) {
            wd[k] = W_b0[SS * SS + ch0 + k];
            bb[k] = b_b0[ch0 + k];
#pragma unroll
            for (int o = 0; o < 10; o++) wb1[k][o] = W_b1[(ch0 + k) * 10 + o];
        }
        float bb1 = (lane < 10) ? b_b1[lane] : 0.f;

        int e = warp0;
        if (e >= EGn) return;
        int j = eig[e];
        int i = eig[EGn + e];
        for (; e < EGn; e += NW_G) {
            // prefetch next edge's indices (breaks idx->gather chain)
            int en = e + NW_G;
            int jn = 0, in_ = 0;
            if (en < EGn) { jn = eig[en]; in_ = eig[EGn + en]; }

            const float4* ui = (const float4*)(u + (size_t)i * SS + ch0);
            const float4* uj = (const float4*)(u + (size_t)j * SS + ch0);
            float4 a0 = __ldg(ui);     float4 a1 = __ldg(ui + 1);
            float4 c0 = __ldg(uj);     float4 c1 = __ldg(uj + 1);

            float pix = g_posc[i * 3 + 0], piy = g_posc[i * 3 + 1], piz = g_posc[i * 3 + 2];
            float pjx = g_posc[j * 3 + 0], pjy = g_posc[j * 3 + 1], pjz = g_posc[j * 3 + 2];
            float rx = pix - pjx, ry = piy - pjy, rz = piz - pjz;
            float ss = rx * rx + ry * ry + rz * rz;
            float db = sqrtf(ss);
            if (lane == 0) {
                out[OFF_AG + e] = pix * pjx + piy * pjy + piz * pjz;
                float inv = rsqrtf(fmaxf(ss, 1e-6f));
                out[OFF_RNG + 3 * e + 0] = rx * inv;
                out[OFF_RNG + 3 * e + 1] = ry * inv;
                out[OFF_RNG + 3 * e + 2] = rz * inv;
            }

            float h[8] = {a0.x + c0.x, a0.y + c0.y, a0.z + c0.z, a0.w + c0.w,
                          a1.x + c1.x, a1.y + c1.y, a1.z + c1.z, a1.w + c1.w};
            float acc[10] = {};
#pragma unroll
            for (int k = 0; k < 8; k++) {
                float pre = fmaf(db, wd[k], h[k] + bb[k]);
                float hv = __fdividef(pre, 1.0f + __expf(-pre));
#pragma unroll
                for (int o = 0; o < 10; o++) acc[o] = fmaf(hv, wb1[k][o], acc[o]);
            }
#pragma unroll
            for (int off = 16; off > 0; off >>= 1) {
#pragma unroll
                for (int o = 0; o < 10; o++)
                    acc[o] += __shfl_xor_sync(0xffffffffu, acc[o], off);
            }
            if (lane < 5)       out[OFF_BP + (size_t)e * 5 + lane] = acc[lane] + bb1;
            else if (lane < 10) out[OFF_BE + (size_t)e * 5 + (lane - 5)] = acc[lane] + bb1;

            j = jn; i = in_;
        }
    } else if (blk < GBLK + ABLK) {
        // ---------------- atoms: h3 @ W_atoms + b_atoms ----------------
        int w = (blk - GBLK) * 8 + (tid >> 5);
        if (w >= NN) return;
        float acc = b_atoms[lane];
        for (int k0 = 0; k0 < SS; k0 += 32) {
            float hv = h3[(size_t)w * SS + k0 + lane];
#pragma unroll
            for (int kk = 0; kk < 32; kk++) {
                float h = __shfl_sync(0xffffffffu, hv, kk);
                acc = fmaf(h, W_atoms[(k0 + kk) * 32 + lane], acc);
            }
        }
        if (lane < NAn) out[OFF_AE + w * NAn + lane] = acc;
        else            out[OFF_AP + w * NAn + (lane - NAn)] = acc;
    } else {
        // ---------------- local edge attrs ----------------
        int e = (blk - GBLK - ABLK) * 256 + tid;
        if (e >= ELn) return;
        int s = eil[e];
        int tg = eil[ELn + e];
        float rx = g_posc[tg * 3 + 0] - g_posc[s * 3 + 0];
        float ry = g_posc[tg * 3 + 1] - g_posc[s * 3 + 1];
        float rz = g_posc[tg * 3 + 2] - g_posc[s * 3 + 2];
        float ss = rx * rx + ry * ry + rz * rz;
        float sc = fmaxf(ss, 1e-6f);
        float d = sqrtf(sc);
        out[OFF_DL + e] = d;
        float inv = rsqrtf(sc);
        out[OFF_RNL + 3 * e + 0] = rx * inv;
        out[OFF_RNL + 3 * e + 1] = ry * inv;
        out[OFF_RNL + 3 * e + 2] = rz * inv;
    }
}

// ============================================================
// Host launcher
// ============================================================
extern "C" void kernel_launch(void* const* d_in, const int* in_sizes, int n_in,
                              void* d_out, int out_size) {
    int iX, iT, iPOS, iWT, iBT, iWA, iBA, iWAT, iBAT, iWSH, iBSH,
        iWB0, iBB0, iWB1, iBB1, iWATM, iBATM, iEIL, iEIG, iBATCH;
    if (in_sizes[3] == 2 * ELn) {
        iX = 0; iT = 1; iPOS = 2; iEIL = 3; iEIG = 4; iBATCH = 6;
        iWT = 7; iBT = 8; iWA = 9; iBA = 10; iWAT = 11; iBAT = 12;
        iWSH = 13; iBSH = 14; iWB0 = 15; iBB0 = 16; iWB1 = 17; iBB1 = 18;
        iWATM = 20; iBATM = 21;
    } else {
        iX = 0; iT = 1; iPOS = 2; iWT = 4; iBT = 5; iWA = 6; iBA = 7;
        iWAT = 8; iBAT = 9; iWSH = 10; iBSH = 11; iWB0 = 12; iBB0 = 13;
        iWB1 = 14; iBB1 = 15; iWATM = 17; iBATM = 18;
        iEIL = 19; iEIG = 20; iBATCH = 21;
    }

    const float* x       = (const float*)d_in[iX];
    const float* t       = (const float*)d_in[iT];
    const float* pos     = (const float*)d_in[iPOS];
    const float* W_time  = (const float*)d_in[iWT];
    const float* b_time  = (const float*)d_in[iBT];
    const float* W_atom  = (const float*)d_in[iWA];
    const float* b_atom  = (const float*)d_in[iBA];
    const float* W_at    = (const float*)d_in[iWAT];
    const float* b_at    = (const float*)d_in[iBAT];
    const float* W_sh    = (const float*)d_in[iWSH];
    const float* b_sh    = (const float*)d_in[iBSH];
    const float* W_b0    = (const float*)d_in[iWB0];
    const float* b_b0    = (const float*)d_in[iBB0];
    const float* W_b1    = (const float*)d_in[iWB1];
    const float* b_b1    = (const float*)d_in[iBB1];
    const float* W_atoms = (const float*)d_in[iWATM];
    const float* b_atoms = (const float*)d_in[iBATM];
    const int* eil       = (const int*)d_in[iEIL];
    const int* eig       = (const int*)d_in[iEIG];
    const int* batch     = (const int*)d_in[iBATCH];
    float* out = (float*)d_out;

    float *bufA, *bufB;
    cudaGetSymbolAddress((void**)&bufA, g_bufA);
    cudaGetSymbolAddress((void**)&bufB, g_bufB);

    // 1
    k_pre<<<GG + NAn + 1, 256>>>(t, W_time, b_time, b_atom, W_at, b_at, W_atom);
    // 2
    k_possum<<<(NN + 255) / 256, 256>>>(pos, batch);
    // 3
    k_center_h2<<<40 + NN, 256>>>(pos, batch, x, out);
    // 4,5
    dim3 gg(2, (NN + 63) / 64);   // (2, 157)
    k_gemm64<1><<<gg, 256>>>(bufA, W_sh, b_sh, bufB);      // h3 -> bufB
    k_gemm64<2><<<gg, 256>>>(bufB, W_b0, nullptr, bufA);   // u  -> bufA
    // 6 (NCU capture window) — fused tail
    k_tail<<<GBLK + ABLK + LBLK, 256>>>(eig, bufA, W_b0, b_b0, W_b1, b_b1,
                                        bufB, W_atoms, b_atoms, eil, out);
}

// round 7
// speedup vs baseline: 1.9738x; 1.1043x over previous
#include <cuda_runtime.h>
#include <math.h>

#define NN   10000
#define GG   200
#define ELn  160000
#define EGn  500000
#define SS   256
#define NAn  16
#define NBn  5

// ---- output offsets (floats) ----
#define OFF_CP   0
#define OFF_CE0  30000
#define OFF_AP   60000
#define OFF_AE   220000
#define OFF_BP   380000
#define OFF_BE   2880000
#define OFF_DL   5380000
#define OFF_RNL  5540000
#define OFF_AG   6020000
#define OFF_RNG  6520000

// ---- tail kernel block partition (128-thread blocks) ----
#define GBLK 2368                 // global-edge blocks (4 warps each)
#define NS   (GBLK * 4)           // 9472 edge slots
#define ABLK 2500                 // atoms blocks (4 nodes each)
#define LBLK 1250                 // local blocks (128 edges each)

// ---- scratch ----
__device__ float g_sum[GG * 3];
__device__ float g_cnt[GG];
__device__ float g_temb2[GG * SS];
__device__ float g_Wc[NAn * SS];
__device__ float g_posc[NN * 3];
__device__ float g_bufA[NN * SS];
__device__ float g_bufB[NN * SS];

// ============================================================
// Launch 1 — k_pre (fused): temb2 / Wc / zero accumulators
// ============================================================
__global__ void __launch_bounds__(256) k_pre(const float* __restrict__ t,
                                             const float* __restrict__ W_time,
                                             const float* __restrict__ b_time,
                                             const float* __restrict__ b_atom,
                                             const float* __restrict__ W_at,
                                             const float* __restrict__ b_at,
                                             const float* __restrict__ W_atom) {
    int b = blockIdx.x;
    int c = threadIdx.x;
    if (b < GG) {
        __shared__ float tin[SS];
        tin[c] = fmaf(t[b], W_time[c], b_time[c]) + b_atom[c];
        __syncthreads();
        float a0 = 0.f, a1 = 0.f, a2 = 0.f, a3 = 0.f;
#pragma unroll 4
        for (int k = 0; k < SS; k += 4) {
            a0 = fmaf(tin[k + 0], W_at[(k + 0) * SS + c], a0);
            a1 = fmaf(tin[k + 1], W_at[(k + 1) * SS + c], a1);
            a2 = fmaf(tin[k + 2], W_at[(k + 2) * SS + c], a2);
            a3 = fmaf(tin[k + 3], W_at[(k + 3) * SS + c], a3);
        }
        g_temb2[b * SS + c] = (a0 + a1) + (a2 + a3) + b_at[c];
    } else if (b < GG + NAn) {
        int r = b - GG;
        __shared__ float arow[SS];
        arow[c] = W_atom[r * SS + c];
        __syncthreads();
        float a0 = 0.f, a1 = 0.f, a2 = 0.f, a3 = 0.f;
#pragma unroll 4
        for (int k = 0; k < SS; k += 4) {
            a0 = fmaf(arow[k + 0], W_at[(k + 0) * SS + c], a0);
            a1 = fmaf(arow[k + 1], W_at[(k + 1) * SS + c], a1);
            a2 = fmaf(arow[k + 2], W_at[(k + 2) * SS + c], a2);
            a3 = fmaf(arow[k + 3], W_at[(k + 3) * SS + c], a3);
        }
        g_Wc[r * SS + c] = (a0 + a1) + (a2 + a3);
    } else {
        for (int i = c; i < GG * 3; i += 256) g_sum[i] = 0.f;
        for (int i = c; i < GG; i += 256)     g_cnt[i] = 0.f;
    }
}

// ============================================================
// Launch 2 — k_possum
// ============================================================
__global__ void k_possum(const float* __restrict__ pos,
                         const int* __restrict__ batch) {
    int n = blockIdx.x * blockDim.x + threadIdx.x;
    if (n >= NN) return;
    int b = batch[n];
    atomicAdd(&g_sum[b * 3 + 0], pos[n * 3 + 0]);
    atomicAdd(&g_sum[b * 3 + 1], pos[n * 3 + 1]);
    atomicAdd(&g_sum[b * 3 + 2], pos[n * 3 + 2]);
    atomicAdd(&g_cnt[b], 1.0f);
}

// ============================================================
// Launch 3 — k_center_h2 (fused)
// ============================================================
__global__ void __launch_bounds__(256) k_center_h2(const float* __restrict__ pos,
                                                   const int* __restrict__ batch,
                                                   const float* __restrict__ x,
                                                   float* __restrict__ out) {
    if (blockIdx.x < 40) {
        int n = blockIdx.x * 256 + threadIdx.x;
        if (n >= NN) return;
        int b = batch[n];
        float inv = 1.0f / fmaxf(g_cnt[b], 1.0f);
#pragma unroll
        for (int k = 0; k < 3; k++) {
            float v = pos[n * 3 + k] - g_sum[b * 3 + k] * inv;
            g_posc[n * 3 + k] = v;
            out[OFF_CP + n * 3 + k] = v;
            out[OFF_CE0 + n * 3 + k] = 0.f;
        }
    } else {
        int n = blockIdx.x - 40;
        int c = threadIdx.x;
        __shared__ float xs[NAn];
        __shared__ int bsh;
        if (c < NAn) xs[c] = x[n * NAn + c];
        if (c == 0) bsh = batch[n];
        __syncthreads();
        float acc = g_temb2[bsh * SS + c];
#pragma unroll
        for (int k = 0; k < NAn; k++) acc = fmaf(xs[k], g_Wc[k * SS + c], acc);
        g_bufA[n * SS + c] = acc;
    }
}

// ============================================================
// Launches 4,5 — fp32 GEMM, 64x128 tile, BK=8, double-buffered
// ACT: 1 = bias+silu, 2 = raw
// ============================================================
template <int ACT>
__global__ void __launch_bounds__(256) k_gemm64(const float* __restrict__ A,
                                                const float* __restrict__ W,
                                                const float* __restrict__ bias,
                                                float* __restrict__ C) {
    __shared__ float As[2][8][68];
    __shared__ float Bs[2][8][128];
    const int tid = threadIdx.x;
    const int row0 = blockIdx.y * 64;
    const int col0 = blockIdx.x * 128;
    const int ar = tid >> 2;
    const int ak = (tid & 3) * 2;
    const int bk = tid >> 5;
    const int bc = (tid & 31) * 4;
    const int ty = tid >> 4;
    const int tx = tid & 15;
    const int arow = row0 + ar;

    {
        float2 av = make_float2(0.f, 0.f);
        if (arow < NN) av = *(const float2*)&A[(size_t)arow * SS + ak];
        float4 bv = *(const float4*)&W[(size_t)bk * SS + col0 + bc];
        As[0][ak + 0][ar] = av.x;
        As[0][ak + 1][ar] = av.y;
        *(float4*)&Bs[0][bk][bc] = bv;
    }
    __syncthreads();

    float acc[4][8] = {};
    for (int k0 = 0; k0 < SS; k0 += 8) {
        const int buf = (k0 >> 3) & 1;
        const bool more = (k0 + 8 < SS);
        float2 nav = make_float2(0.f, 0.f);
        float4 nbv;
        if (more) {
            if (arow < NN) nav = *(const float2*)&A[(size_t)arow * SS + k0 + 8 + ak];
            nbv = *(const float4*)&W[(size_t)(k0 + 8 + bk) * SS + col0 + bc];
        }
#pragma unroll
        for (int k = 0; k < 8; k++) {
            float a[4], b[8];
            *(float4*)&a[0] = *(const float4*)&As[buf][k][ty * 4];
            *(float4*)&b[0] = *(const float4*)&Bs[buf][k][tx * 4];
            *(float4*)&b[4] = *(const float4*)&Bs[buf][k][64 + tx * 4];
#pragma unroll
            for (int i = 0; i < 4; i++)
#pragma unroll
                for (int j = 0; j < 8; j++)
                    acc[i][j] = fmaf(a[i], b[j], acc[i][j]);
        }
        if (more) {
            As[buf ^ 1][ak + 0][ar] = nav.x;
            As[buf ^ 1][ak + 1][ar] = nav.y;
            *(float4*)&Bs[buf ^ 1][bk][bc] = nbv;
            __syncthreads();
        }
    }

#pragma unroll
    for (int i = 0; i < 4; i++) {
        int row = row0 + ty * 4 + i;
        if (row >= NN) continue;
#pragma unroll
        for (int half = 0; half < 2; half++) {
            int col = col0 + half * 64 + tx * 4;
            float4 v;
            v.x = acc[i][half * 4 + 0];
            v.y = acc[i][half * 4 + 1];
            v.z = acc[i][half * 4 + 2];
            v.w = acc[i][half * 4 + 3];
            if (ACT != 2) {
                v.x += bias[col + 0];
                v.y += bias[col + 1];
                v.z += bias[col + 2];
                v.w += bias[col + 3];
            }
            if (ACT == 1) {
                v.x = __fdividef(v.x, 1.0f + __expf(-v.x));
                v.y = __fdividef(v.y, 1.0f + __expf(-v.y));
                v.z = __fdividef(v.z, 1.0f + __expf(-v.z));
                v.w = __fdividef(v.w, 1.0f + __expf(-v.w));
            }
            *(float4*)&C[(size_t)row * SS + col] = v;
        }
    }
}

// ============================================================
// Launch 6 — k_tail (fused, 128-thread blocks):
//   blocks [0,GBLK): global edges, warp per edge-slot,
//     indices prefetched 2 ahead, u-rows prefetched 1 ahead
//   blocks [GBLK,GBLK+ABLK): atoms
//   rest: local edges
// ============================================================
__global__ void __launch_bounds__(128, 3) k_tail(const int* __restrict__ eig,
                                                 const float* __restrict__ u,
                                                 const float* __restrict__ W_b0,
                                                 const float* __restrict__ b_b0,
                                                 const float* __restrict__ W_b1,
                                                 const float* __restrict__ b_b1,
                                                 const float* __restrict__ h3,
                                                 const float* __restrict__ W_atoms,
                                                 const float* __restrict__ b_atoms,
                                                 const int* __restrict__ eil,
                                                 float* __restrict__ out) {
    const int blk = blockIdx.x;
    const int tid = threadIdx.x;
    const int lane = tid & 31;

    if (blk < GBLK) {
        // ---------------- global edges ----------------
        const int slot = blk * 4 + (tid >> 5);
        const int ch0 = lane * 8;

        float wb1[8][10];
        float wd[8], bb[8];
#pragma unroll
        for (int k = 0; k < 8; k++) {
            wd[k] = W_b0[SS * SS + ch0 + k];
            bb[k] = b_b0[ch0 + k];
#pragma unroll
            for (int o = 0; o < 10; o++) wb1[k][o] = W_b1[(ch0 + k) * 10 + o];
        }
        float bb1 = (lane < 10) ? b_b1[lane] : 0.f;

        int e = slot;
        if (e >= EGn) return;
        // current edge state
        int j1 = eig[e];
        int i1 = eig[EGn + e];
        const float4* p;
        p = (const float4*)(u + (size_t)i1 * SS + ch0);
        float4 A0 = __ldg(p), A1 = __ldg(p + 1);
        p = (const float4*)(u + (size_t)j1 * SS + ch0);
        float4 C0 = __ldg(p), C1 = __ldg(p + 1);
        // next edge indices
        int e2 = e + NS;
        int j2 = 0, i2 = 0;
        if (e2 < EGn) { j2 = eig[e2]; i2 = eig[EGn + e2]; }

        while (e < EGn) {
            // prefetch idx two ahead
            int e3 = e2 + NS;
            int j3 = 0, i3 = 0;
            if (e3 < EGn) { j3 = eig[e3]; i3 = eig[EGn + e3]; }
            // prefetch u rows one ahead
            float4 B0 = make_float4(0.f, 0.f, 0.f, 0.f), B1 = B0, D0 = B0, D1 = B0;
            if (e2 < EGn) {
                p = (const float4*)(u + (size_t)i2 * SS + ch0);
                B0 = __ldg(p); B1 = __ldg(p + 1);
                p = (const float4*)(u + (size_t)j2 * SS + ch0);
                D0 = __ldg(p); D1 = __ldg(p + 1);
            }

            // compute current edge
            float pix = g_posc[i1 * 3 + 0], piy = g_posc[i1 * 3 + 1], piz = g_posc[i1 * 3 + 2];
            float pjx = g_posc[j1 * 3 + 0], pjy = g_posc[j1 * 3 + 1], pjz = g_posc[j1 * 3 + 2];
            float rx = pix - pjx, ry = piy - pjy, rz = piz - pjz;
            float ss = rx * rx + ry * ry + rz * rz;
            float db = sqrtf(ss);
            if (lane == 0) {
                out[OFF_AG + e] = pix * pjx + piy * pjy + piz * pjz;
                float inv = rsqrtf(fmaxf(ss, 1e-6f));
                out[OFF_RNG + 3 * e + 0] = rx * inv;
                out[OFF_RNG + 3 * e + 1] = ry * inv;
                out[OFF_RNG + 3 * e + 2] = rz * inv;
            }

            float h[8] = {A0.x + C0.x, A0.y + C0.y, A0.z + C0.z, A0.w + C0.w,
                          A1.x + C1.x, A1.y + C1.y, A1.z + C1.z, A1.w + C1.w};
            float acc[10] = {};
#pragma unroll
            for (int k = 0; k < 8; k++) {
                float pre = fmaf(db, wd[k], h[k] + bb[k]);
                float hv = __fdividef(pre, 1.0f + __expf(-pre));
#pragma unroll
                for (int o = 0; o < 10; o++) acc[o] = fmaf(hv, wb1[k][o], acc[o]);
            }
#pragma unroll
            for (int off = 16; off > 0; off >>= 1) {
#pragma unroll
                for (int o = 0; o < 10; o++)
                    acc[o] += __shfl_xor_sync(0xffffffffu, acc[o], off);
            }
            if (lane < 5)       out[OFF_BP + (size_t)e * 5 + lane] = acc[lane] + bb1;
            else if (lane < 10) out[OFF_BE + (size_t)e * 5 + (lane - 5)] = acc[lane] + bb1;

            // rotate pipeline
            e = e2; i1 = i2; j1 = j2;
            A0 = B0; A1 = B1; C0 = D0; C1 = D1;
            e2 = e3; i2 = i3; j2 = j3;
        }
    } else if (blk < GBLK + ABLK) {
        // ---------------- atoms ----------------
        int w = (blk - GBLK) * 4 + (tid >> 5);
        if (w >= NN) return;
        float acc = b_atoms[lane];
        for (int k0 = 0; k0 < SS; k0 += 32) {
            float hv = h3[(size_t)w * SS + k0 + lane];
#pragma unroll
            for (int kk = 0; kk < 32; kk++) {
                float h = __shfl_sync(0xffffffffu, hv, kk);
                acc = fmaf(h, W_atoms[(k0 + kk) * 32 + lane], acc);
            }
        }
        if (lane < NAn) out[OFF_AE + w * NAn + lane] = acc;
        else            out[OFF_AP + w * NAn + (lane - NAn)] = acc;
    } else {
        // ---------------- local edges ----------------
        int e = (blk - GBLK - ABLK) * 128 + tid;
        if (e >= ELn) return;
        int s = eil[e];
        int tg = eil[ELn + e];
        float rx = g_posc[tg * 3 + 0] - g_posc[s * 3 + 0];
        float ry = g_posc[tg * 3 + 1] - g_posc[s * 3 + 1];
        float rz = g_posc[tg * 3 + 2] - g_posc[s * 3 + 2];
        float ss = rx * rx + ry * ry + rz * rz;
        float sc = fmaxf(ss, 1e-6f);
        float d = sqrtf(sc);
        out[OFF_DL + e] = d;
        float inv = rsqrtf(sc);
        out[OFF_RNL + 3 * e + 0] = rx * inv;
        out[OFF_RNL + 3 * e + 1] = ry * inv;
        out[OFF_RNL + 3 * e + 2] = rz * inv;
    }
}

// ============================================================
// Host launcher
// ============================================================
extern "C" void kernel_launch(void* const* d_in, const int* in_sizes, int n_in,
                              void* d_out, int out_size) {
    int iX, iT, iPOS, iWT, iBT, iWA, iBA, iWAT, iBAT, iWSH, iBSH,
        iWB0, iBB0, iWB1, iBB1, iWATM, iBATM, iEIL, iEIG, iBATCH;
    if (in_sizes[3] == 2 * ELn) {
        iX = 0; iT = 1; iPOS = 2; iEIL = 3; iEIG = 4; iBATCH = 6;
        iWT = 7; iBT = 8; iWA = 9; iBA = 10; iWAT = 11; iBAT = 12;
        iWSH = 13; iBSH = 14; iWB0 = 15; iBB0 = 16; iWB1 = 17; iBB1 = 18;
        iWATM = 20; iBATM = 21;
    } else {
        iX = 0; iT = 1; iPOS = 2; iWT = 4; iBT = 5; iWA = 6; iBA = 7;
        iWAT = 8; iBAT = 9; iWSH = 10; iBSH = 11; iWB0 = 12; iBB0 = 13;
        iWB1 = 14; iBB1 = 15; iWATM = 17; iBATM = 18;
        iEIL = 19; iEIG = 20; iBATCH = 21;
    }

    const float* x       = (const float*)d_in[iX];
    const float* t       = (const float*)d_in[iT];
    const float* pos     = (const float*)d_in[iPOS];
    const float* W_time  = (const float*)d_in[iWT];
    const float* b_time  = (const float*)d_in[iBT];
    const float* W_atom  = (const float*)d_in[iWA];
    const float* b_atom  = (const float*)d_in[iBA];
    const float* W_at    = (const float*)d_in[iWAT];
    const float* b_at    = (const float*)d_in[iBAT];
    const float* W_sh    = (const float*)d_in[iWSH];
    const float* b_sh    = (const float*)d_in[iBSH];
    const float* W_b0    = (const float*)d_in[iWB0];
    const float* b_b0    = (const float*)d_in[iBB0];
    const float* W_b1    = (const float*)d_in[iWB1];
    const float* b_b1    = (const float*)d_in[iBB1];
    const float* W_atoms = (const float*)d_in[iWATM];
    const float* b_atoms = (const float*)d_in[iBATM];
    const int* eil       = (const int*)d_in[iEIL];
    const int* eig       = (const int*)d_in[iEIG];
    const int* batch     = (const int*)d_in[iBATCH];
    float* out = (float*)d_out;

    float *bufA, *bufB;
    cudaGetSymbolAddress((void**)&bufA, g_bufA);
    cudaGetSymbolAddress((void**)&bufB, g_bufB);

    // 1
    k_pre<<<GG + NAn + 1, 256>>>(t, W_time, b_time, b_atom, W_at, b_at, W_atom);
    // 2
    k_possum<<<(NN + 255) / 256, 256>>>(pos, batch);
    // 3
    k_center_h2<<<40 + NN, 256>>>(pos, batch, x, out);
    // 4,5
    dim3 gg(2, (NN + 63) / 64);   // (2, 157)
    k_gemm64<1><<<gg, 256>>>(bufA, W_sh, b_sh, bufB);      // h3 -> bufB
    k_gemm64<2><<<gg, 256>>>(bufB, W_b0, nullptr, bufA);   // u  -> bufA
    // 6 — fused tail (NCU capture window)
    k_tail<<<GBLK + ABLK + LBLK, 128>>>(eig, bufA, W_b0, b_b0, W_b1, b_b1,
                                        bufB, W_atoms, b_atoms, eil, out);
}

// round 8
// speedup vs baseline: 2.0638x; 1.0456x over previous
#include <cuda_runtime.h>
#include <math.h>

#define NN   10000
#define GG   200
#define ELn  160000
#define EGn  500000
#define SS   256
#define NAn  16
#define NBn  5

// ---- output offsets (floats) ----
#define OFF_CP   0
#define OFF_CE0  30000
#define OFF_AP   60000
#define OFF_AE   220000
#define OFF_BP   380000
#define OFF_BE   2880000
#define OFF_DL   5380000
#define OFF_RNL  5540000
#define OFF_AG   6020000
#define OFF_RNG  6520000

// ---- tail kernel block partition (128-thread blocks) ----
#define GBLK 2368                 // global-edge blocks (4 warps each)
#define NS   (GBLK * 4)           // 9472 edge slots
#define ABLK 2500                 // atoms blocks (4 nodes each)
#define LBLK 1250                 // local blocks (128 edges each)

// ---- scratch ----
__device__ float g_sum[GG * 3];
__device__ float g_cnt[GG];
__device__ float g_temb2[GG * SS];
__device__ float g_Wc[NAn * SS];
__device__ float g_hbias[SS];      // 0.5 * b_b0
__device__ float g_posc[NN * 3];
__device__ float g_bufA[NN * SS];
__device__ float g_bufB[NN * SS];

// ============================================================
// Launch 1 — k_pre (fused): temb2 / Wc / zero accumulators + hbias
// ============================================================
__global__ void __launch_bounds__(256) k_pre(const float* __restrict__ t,
                                             const float* __restrict__ W_time,
                                             const float* __restrict__ b_time,
                                             const float* __restrict__ b_atom,
                                             const float* __restrict__ W_at,
                                             const float* __restrict__ b_at,
                                             const float* __restrict__ W_atom,
                                             const float* __restrict__ b_b0) {
    int b = blockIdx.x;
    int c = threadIdx.x;
    if (b < GG) {
        __shared__ float tin[SS];
        tin[c] = fmaf(t[b], W_time[c], b_time[c]) + b_atom[c];
        __syncthreads();
        float a0 = 0.f, a1 = 0.f, a2 = 0.f, a3 = 0.f;
#pragma unroll 4
        for (int k = 0; k < SS; k += 4) {
            a0 = fmaf(tin[k + 0], W_at[(k + 0) * SS + c], a0);
            a1 = fmaf(tin[k + 1], W_at[(k + 1) * SS + c], a1);
            a2 = fmaf(tin[k + 2], W_at[(k + 2) * SS + c], a2);
            a3 = fmaf(tin[k + 3], W_at[(k + 3) * SS + c], a3);
        }
        g_temb2[b * SS + c] = (a0 + a1) + (a2 + a3) + b_at[c];
    } else if (b < GG + NAn) {
        int r = b - GG;
        __shared__ float arow[SS];
        arow[c] = W_atom[r * SS + c];
        __syncthreads();
        float a0 = 0.f, a1 = 0.f, a2 = 0.f, a3 = 0.f;
#pragma unroll 4
        for (int k = 0; k < SS; k += 4) {
            a0 = fmaf(arow[k + 0], W_at[(k + 0) * SS + c], a0);
            a1 = fmaf(arow[k + 1], W_at[(k + 1) * SS + c], a1);
            a2 = fmaf(arow[k + 2], W_at[(k + 2) * SS + c], a2);
            a3 = fmaf(arow[k + 3], W_at[(k + 3) * SS + c], a3);
        }
        g_Wc[r * SS + c] = (a0 + a1) + (a2 + a3);
    } else {
        g_hbias[c] = 0.5f * b_b0[c];
        for (int i = c; i < GG * 3; i += 256) g_sum[i] = 0.f;
        for (int i = c; i < GG; i += 256)     g_cnt[i] = 0.f;
    }
}

// ============================================================
// Launch 2 — k_possum
// ============================================================
__global__ void k_possum(const float* __restrict__ pos,
                         const int* __restrict__ batch) {
    int n = blockIdx.x * blockDim.x + threadIdx.x;
    if (n >= NN) return;
    int b = batch[n];
    atomicAdd(&g_sum[b * 3 + 0], pos[n * 3 + 0]);
    atomicAdd(&g_sum[b * 3 + 1], pos[n * 3 + 1]);
    atomicAdd(&g_sum[b * 3 + 2], pos[n * 3 + 2]);
    atomicAdd(&g_cnt[b], 1.0f);
}

// ============================================================
// Launch 3 — k_center_h2 (fused)
// ============================================================
__global__ void __launch_bounds__(256) k_center_h2(const float* __restrict__ pos,
                                                   const int* __restrict__ batch,
                                                   const float* __restrict__ x,
                                                   float* __restrict__ out) {
    if (blockIdx.x < 40) {
        int n = blockIdx.x * 256 + threadIdx.x;
        if (n >= NN) return;
        int b = batch[n];
        float inv = 1.0f / fmaxf(g_cnt[b], 1.0f);
#pragma unroll
        for (int k = 0; k < 3; k++) {
            float v = pos[n * 3 + k] - g_sum[b * 3 + k] * inv;
            g_posc[n * 3 + k] = v;
            out[OFF_CP + n * 3 + k] = v;
            out[OFF_CE0 + n * 3 + k] = 0.f;
        }
    } else {
        int n = blockIdx.x - 40;
        int c = threadIdx.x;
        __shared__ float xs[NAn];
        __shared__ int bsh;
        if (c < NAn) xs[c] = x[n * NAn + c];
        if (c == 0) bsh = batch[n];
        __syncthreads();
        float acc = g_temb2[bsh * SS + c];
#pragma unroll
        for (int k = 0; k < NAn; k++) acc = fmaf(xs[k], g_Wc[k * SS + c], acc);
        g_bufA[n * SS + c] = acc;
    }
}

// ============================================================
// Launches 4,5 — fp32 GEMM, 64x128 tile, BK=16, double-buffered
// ACT: 0 = bias only, 1 = bias + silu
// ============================================================
template <int ACT>
__global__ void __launch_bounds__(256) k_gemm64(const float* __restrict__ A,
                                                const float* __restrict__ W,
                                                const float* __restrict__ bias,
                                                float* __restrict__ C) {
    __shared__ float As[2][16][68];
    __shared__ float Bs[2][16][128];
    const int tid = threadIdx.x;
    const int row0 = blockIdx.y * 64;
    const int col0 = blockIdx.x * 128;
    const int ar = tid >> 2;            // 0..63 (A row)
    const int ak = (tid & 3) * 4;       // 0,4,8,12 (A k-offset, float4)
    const int bk = tid >> 4;            // 0..15 (B k-row)
    const int bc = (tid & 15) * 8;      // 0..120 (B col, 2x float4)
    const int ty = tid >> 4;            // 0..15 (4 rows)
    const int tx = tid & 15;            // 0..15 (8 cols split 4+4)
    const int arow = row0 + ar;

    // prologue: tile 0 -> buf 0
    {
        float4 av = make_float4(0.f, 0.f, 0.f, 0.f);
        if (arow < NN) av = *(const float4*)&A[(size_t)arow * SS + ak];
        As[0][ak + 0][ar] = av.x;
        As[0][ak + 1][ar] = av.y;
        As[0][ak + 2][ar] = av.z;
        As[0][ak + 3][ar] = av.w;
        *(float4*)&Bs[0][bk][bc]     = *(const float4*)&W[(size_t)bk * SS + col0 + bc];
        *(float4*)&Bs[0][bk][bc + 4] = *(const float4*)&W[(size_t)bk * SS + col0 + bc + 4];
    }
    __syncthreads();

    float acc[4][8] = {};
    for (int k0 = 0; k0 < SS; k0 += 16) {
        const int buf = (k0 >> 4) & 1;
        const bool more = (k0 + 16 < SS);
        float4 nav = make_float4(0.f, 0.f, 0.f, 0.f);
        float4 nbv0, nbv1;
        if (more) {
            if (arow < NN) nav = *(const float4*)&A[(size_t)arow * SS + k0 + 16 + ak];
            nbv0 = *(const float4*)&W[(size_t)(k0 + 16 + bk) * SS + col0 + bc];
            nbv1 = *(const float4*)&W[(size_t)(k0 + 16 + bk) * SS + col0 + bc + 4];
        }
#pragma unroll
        for (int k = 0; k < 16; k++) {
            float a[4], b[8];
            *(float4*)&a[0] = *(const float4*)&As[buf][k][ty * 4];
            *(float4*)&b[0] = *(const float4*)&Bs[buf][k][tx * 4];
            *(float4*)&b[4] = *(const float4*)&Bs[buf][k][64 + tx * 4];
#pragma unroll
            for (int i = 0; i < 4; i++)
#pragma unroll
                for (int j = 0; j < 8; j++)
                    acc[i][j] = fmaf(a[i], b[j], acc[i][j]);
        }
        if (more) {
            As[buf ^ 1][ak + 0][ar] = nav.x;
            As[buf ^ 1][ak + 1][ar] = nav.y;
            As[buf ^ 1][ak + 2][ar] = nav.z;
            As[buf ^ 1][ak + 3][ar] = nav.w;
            *(float4*)&Bs[buf ^ 1][bk][bc]     = nbv0;
            *(float4*)&Bs[buf ^ 1][bk][bc + 4] = nbv1;
            __syncthreads();
        }
    }

#pragma unroll
    for (int i = 0; i < 4; i++) {
        int row = row0 + ty * 4 + i;
        if (row >= NN) continue;
#pragma unroll
        for (int half = 0; half < 2; half++) {
            int col = col0 + half * 64 + tx * 4;
            float4 v;
            v.x = acc[i][half * 4 + 0] + bias[col + 0];
            v.y = acc[i][half * 4 + 1] + bias[col + 1];
            v.z = acc[i][half * 4 + 2] + bias[col + 2];
            v.w = acc[i][half * 4 + 3] + bias[col + 3];
            if (ACT == 1) {
                v.x = __fdividef(v.x, 1.0f + __expf(-v.x));
                v.y = __fdividef(v.y, 1.0f + __expf(-v.y));
                v.z = __fdividef(v.z, 1.0f + __expf(-v.z));
                v.w = __fdividef(v.w, 1.0f + __expf(-v.w));
            }
            *(float4*)&C[(size_t)row * SS + col] = v;
        }
    }
}

// ============================================================
// Launch 6 — k_tail (fused, 128-thread blocks):
//   global edges: idx prefetched 2 ahead, u-rows AND pos 1 ahead
//   then atoms, then local edges
// ============================================================
__global__ void __launch_bounds__(128, 3) k_tail(const int* __restrict__ eig,
                                                 const float* __restrict__ u,
                                                 const float* __restrict__ W_b0,
                                                 const float* __restrict__ W_b1,
                                                 const float* __restrict__ b_b1,
                                                 const float* __restrict__ h3,
                                                 const float* __restrict__ W_atoms,
                                                 const float* __restrict__ b_atoms,
                                                 const int* __restrict__ eil,
                                                 float* __restrict__ out) {
    const int blk = blockIdx.x;
    const int tid = threadIdx.x;
    const int lane = tid & 31;

    if (blk < GBLK) {
        // ---------------- global edges ----------------
        const int slot = blk * 4 + (tid >> 5);
        const int ch0 = lane * 8;

        float wb1[8][10];
        float wd[8];
#pragma unroll
        for (int k = 0; k < 8; k++) {
            wd[k] = W_b0[SS * SS + ch0 + k];
#pragma unroll
            for (int o = 0; o < 10; o++) wb1[k][o] = W_b1[(ch0 + k) * 10 + o];
        }
        float bb1 = (lane < 10) ? b_b1[lane] : 0.f;

        int e = slot;
        if (e >= EGn) return;
        // current edge state: idx, u rows, pos
        int j1 = eig[e];
        int i1 = eig[EGn + e];
        const float4* p;
        p = (const float4*)(u + (size_t)i1 * SS + ch0);
        float4 A0 = __ldg(p), A1 = __ldg(p + 1);
        p = (const float4*)(u + (size_t)j1 * SS + ch0);
        float4 C0 = __ldg(p), C1 = __ldg(p + 1);
        float pix1 = g_posc[i1 * 3 + 0], piy1 = g_posc[i1 * 3 + 1], piz1 = g_posc[i1 * 3 + 2];
        float pjx1 = g_posc[j1 * 3 + 0], pjy1 = g_posc[j1 * 3 + 1], pjz1 = g_posc[j1 * 3 + 2];
        // next edge indices
        int e2 = e + NS;
        int j2 = 0, i2 = 0;
        if (e2 < EGn) { j2 = eig[e2]; i2 = eig[EGn + e2]; }

        while (e < EGn) {
            // prefetch idx two ahead
            int e3 = e2 + NS;
            int j3 = 0, i3 = 0;
            if (e3 < EGn) { j3 = eig[e3]; i3 = eig[EGn + e3]; }
            // prefetch u rows + pos one ahead
            float4 B0 = make_float4(0.f, 0.f, 0.f, 0.f), B1 = B0, D0 = B0, D1 = B0;
            float pix2 = 0.f, piy2 = 0.f, piz2 = 0.f, pjx2 = 0.f, pjy2 = 0.f, pjz2 = 0.f;
            if (e2 < EGn) {
                p = (const float4*)(u + (size_t)i2 * SS + ch0);
                B0 = __ldg(p); B1 = __ldg(p + 1);
                p = (const float4*)(u + (size_t)j2 * SS + ch0);
                D0 = __ldg(p); D1 = __ldg(p + 1);
                pix2 = g_posc[i2 * 3 + 0]; piy2 = g_posc[i2 * 3 + 1]; piz2 = g_posc[i2 * 3 + 2];
                pjx2 = g_posc[j2 * 3 + 0]; pjy2 = g_posc[j2 * 3 + 1]; pjz2 = g_posc[j2 * 3 + 2];
            }

            // compute current edge (all operands already in registers)
            float rx = pix1 - pjx1, ry = piy1 - pjy1, rz = piz1 - pjz1;
            float ss = rx * rx + ry * ry + rz * rz;
            float db = sqrtf(ss);
            if (lane == 0) {
                out[OFF_AG + e] = pix1 * pjx1 + piy1 * pjy1 + piz1 * pjz1;
                float inv = rsqrtf(fmaxf(ss, 1e-6f));
                out[OFF_RNG + 3 * e + 0] = rx * inv;
                out[OFF_RNG + 3 * e + 1] = ry * inv;
                out[OFF_RNG + 3 * e + 2] = rz * inv;
            }

            float h[8] = {A0.x + C0.x, A0.y + C0.y, A0.z + C0.z, A0.w + C0.w,
                          A1.x + C1.x, A1.y + C1.y, A1.z + C1.z, A1.w + C1.w};
            float acc[10] = {};
#pragma unroll
            for (int k = 0; k < 8; k++) {
                float pre = fmaf(db, wd[k], h[k]);   // b_b0 folded into u
                float hv = __fdividef(pre, 1.0f + __expf(-pre));
#pragma unroll
                for (int o = 0; o < 10; o++) acc[o] = fmaf(hv, wb1[k][o], acc[o]);
            }
#pragma unroll
            for (int off = 16; off > 0; off >>= 1) {
#pragma unroll
                for (int o = 0; o < 10; o++)
                    acc[o] += __shfl_xor_sync(0xffffffffu, acc[o], off);
            }
            if (lane < 5)       out[OFF_BP + (size_t)e * 5 + lane] = acc[lane] + bb1;
            else if (lane < 10) out[OFF_BE + (size_t)e * 5 + (lane - 5)] = acc[lane] + bb1;

            // rotate pipeline
            e = e2; i1 = i2; j1 = j2;
            A0 = B0; A1 = B1; C0 = D0; C1 = D1;
            pix1 = pix2; piy1 = piy2; piz1 = piz2;
            pjx1 = pjx2; pjy1 = pjy2; pjz1 = pjz2;
            e2 = e3; i2 = i3; j2 = j3;
        }
    } else if (blk < GBLK + ABLK) {
        // ---------------- atoms ----------------
        int w = (blk - GBLK) * 4 + (tid >> 5);
        if (w >= NN) return;
        float acc = b_atoms[lane];
        for (int k0 = 0; k0 < SS; k0 += 32) {
            float hv = h3[(size_t)w * SS + k0 + lane];
#pragma unroll
            for (int kk = 0; kk < 32; kk++) {
                float h = __shfl_sync(0xffffffffu, hv, kk);
                acc = fmaf(h, W_atoms[(k0 + kk) * 32 + lane], acc);
            }
        }
        if (lane < NAn) out[OFF_AE + w * NAn + lane] = acc;
        else            out[OFF_AP + w * NAn + (lane - NAn)] = acc;
    } else {
        // ---------------- local edges ----------------
        int e = (blk - GBLK - ABLK) * 128 + tid;
        if (e >= ELn) return;
        int s = eil[e];
        int tg = eil[ELn + e];
        float rx = g_posc[tg * 3 + 0] - g_posc[s * 3 + 0];
        float ry = g_posc[tg * 3 + 1] - g_posc[s * 3 + 1];
        float rz = g_posc[tg * 3 + 2] - g_posc[s * 3 + 2];
        float ss = rx * rx + ry * ry + rz * rz;
        float sc = fmaxf(ss, 1e-6f);
        float d = sqrtf(sc);
        out[OFF_DL + e] = d;
        float inv = rsqrtf(sc);
        out[OFF_RNL + 3 * e + 0] = rx * inv;
        out[OFF_RNL + 3 * e + 1] = ry * inv;
        out[OFF_RNL + 3 * e + 2] = rz * inv;
    }
}

// ============================================================
// Host launcher
// ============================================================
extern "C" void kernel_launch(void* const* d_in, const int* in_sizes, int n_in,
                              void* d_out, int out_size) {
    int iX, iT, iPOS, iWT, iBT, iWA, iBA, iWAT, iBAT, iWSH, iBSH,
        iWB0, iBB0, iWB1, iBB1, iWATM, iBATM, iEIL, iEIG, iBATCH;
    if (in_sizes[3] == 2 * ELn) {
        iX = 0; iT = 1; iPOS = 2; iEIL = 3; iEIG = 4; iBATCH = 6;
        iWT = 7; iBT = 8; iWA = 9; iBA = 10; iWAT = 11; iBAT = 12;
        iWSH = 13; iBSH = 14; iWB0 = 15; iBB0 = 16; iWB1 = 17; iBB1 = 18;
        iWATM = 20; iBATM = 21;
    } else {
        iX = 0; iT = 1; iPOS = 2; iWT = 4; iBT = 5; iWA = 6; iBA = 7;
        iWAT = 8; iBAT = 9; iWSH = 10; iBSH = 11; iWB0 = 12; iBB0 = 13;
        iWB1 = 14; iBB1 = 15; iWATM = 17; iBATM = 18;
        iEIL = 19; iEIG = 20; iBATCH = 21;
    }

    const float* x       = (const float*)d_in[iX];
    const float* t       = (const float*)d_in[iT];
    const float* pos     = (const float*)d_in[iPOS];
    const float* W_time  = (const float*)d_in[iWT];
    const float* b_time  = (const float*)d_in[iBT];
    const float* W_atom  = (const float*)d_in[iWA];
    const float* b_atom  = (const float*)d_in[iBA];
    const float* W_at    = (const float*)d_in[iWAT];
    const float* b_at    = (const float*)d_in[iBAT];
    const float* W_sh    = (const float*)d_in[iWSH];
    const float* b_sh    = (const float*)d_in[iBSH];
    const float* W_b0    = (const float*)d_in[iWB0];
    const float* b_b0    = (const float*)d_in[iBB0];
    const float* W_b1    = (const float*)d_in[iWB1];
    const float* b_b1    = (const float*)d_in[iBB1];
    const float* W_atoms = (const float*)d_in[iWATM];
    const float* b_atoms = (const float*)d_in[iBATM];
    const int* eil       = (const int*)d_in[iEIL];
    const int* eig       = (const int*)d_in[iEIG];
    const int* batch     = (const int*)d_in[iBATCH];
    float* out = (float*)d_out;

    float *bufA, *bufB, *hbias;
    cudaGetSymbolAddress((void**)&bufA, g_bufA);
    cudaGetSymbolAddress((void**)&bufB, g_bufB);
    cudaGetSymbolAddress((void**)&hbias, g_hbias);

    // 1
    k_pre<<<GG + NAn + 1, 256>>>(t, W_time, b_time, b_atom, W_at, b_at, W_atom, b_b0);
    // 2
    k_possum<<<(NN + 255) / 256, 256>>>(pos, batch);
    // 3
    k_center_h2<<<40 + NN, 256>>>(pos, batch, x, out);
    // 4,5
    dim3 gg(2, (NN + 63) / 64);   // (2, 157)
    k_gemm64<1><<<gg, 256>>>(bufA, W_sh, b_sh, bufB);      // h3 -> bufB
    k_gemm64<0><<<gg, 256>>>(bufB, W_b0, hbias, bufA);     // u + 0.5*b_b0 -> bufA
    // 6 — fused tail
    k_tail<<<GBLK + ABLK + LBLK, 128>>>(eig, bufA, W_b0, W_b1, b_b1,
                                        bufB, W_atoms, b_atoms, eil, out);
}

// round 10
// speedup vs baseline: 2.2447x; 1.0876x over previous
#include <cuda_runtime.h>
#include <math.h>

#define NN   10000
#define GG   200
#define ELn  160000
#define EGn  500000
#define SS   256
#define NAn  16
#define NBn  5

// ---- output offsets (floats) ----
#define OFF_CP   0
#define OFF_CE0  30000
#define OFF_AP   60000
#define OFF_AE   220000
#define OFF_BP   380000
#define OFF_BE   2880000
#define OFF_DL   5380000
#define OFF_RNL  5540000
#define OFF_AG   6020000
#define OFF_RNG  6520000

// ---- tail kernel block partition (128-thread blocks) ----
#define GBLK 2368
#define NS   (GBLK * 4)
#define ABLK 2500
#define LBLK 1250

typedef unsigned long long ull;

// ---- packed f32x2 helpers (sm_103a) ----
__device__ __forceinline__ ull f2pk(float lo, float hi) {
    ull r; asm("mov.b64 %0, {%1, %2};" : "=l"(r) : "f"(lo), "f"(hi)); return r;
}
__device__ __forceinline__ void f2upk(ull v, float& lo, float& hi) {
    asm("mov.b64 {%0, %1}, %2;" : "=f"(lo), "=f"(hi) : "l"(v));
}
__device__ __forceinline__ ull f2fma(ull a, ull b, ull c) {
    ull d; asm("fma.rn.f32x2 %0, %1, %2, %3;" : "=l"(d) : "l"(a), "l"(b), "l"(c)); return d;
}
__device__ __forceinline__ ull f2add(ull a, ull b) {
    ull d; asm("add.rn.f32x2 %0, %1, %2;" : "=l"(d) : "l"(a), "l"(b)); return d;
}

// ---- scratch ----
__device__ float g_sum[GG * 3];
__device__ float g_cnt[GG];
__device__ float g_temb2[GG * SS];
__device__ float g_Wc[NAn * SS];
__device__ float g_hbias[SS];      // 0.5 * b_b0
__device__ float g_posc[NN * 3];
__device__ float g_bufA[NN * SS];
__device__ float g_bufB[NN * SS];

// ============================================================
// Launch 1 — k_pre
// ============================================================
__global__ void __launch_bounds__(256) k_pre(const float* __restrict__ t,
                                             const float* __restrict__ W_time,
                                             const float* __restrict__ b_time,
                                             const float* __restrict__ b_atom,
                                             const float* __restrict__ W_at,
                                             const float* __restrict__ b_at,
                                             const float* __restrict__ W_atom,
                                             const float* __restrict__ b_b0) {
    int b = blockIdx.x;
    int c = threadIdx.x;
    if (b < GG) {
        __shared__ float tin[SS];
        tin[c] = fmaf(t[b], W_time[c], b_time[c]) + b_atom[c];
        __syncthreads();
        float a0 = 0.f, a1 = 0.f, a2 = 0.f, a3 = 0.f;
#pragma unroll 4
        for (int k = 0; k < SS; k += 4) {
            a0 = fmaf(tin[k + 0], W_at[(k + 0) * SS + c], a0);
            a1 = fmaf(tin[k + 1], W_at[(k + 1) * SS + c], a1);
            a2 = fmaf(tin[k + 2], W_at[(k + 2) * SS + c], a2);
            a3 = fmaf(tin[k + 3], W_at[(k + 3) * SS + c], a3);
        }
        g_temb2[b * SS + c] = (a0 + a1) + (a2 + a3) + b_at[c];
    } else if (b < GG + NAn) {
        int r = b - GG;
        __shared__ float arow[SS];
        arow[c] = W_atom[r * SS + c];
        __syncthreads();
        float a0 = 0.f, a1 = 0.f, a2 = 0.f, a3 = 0.f;
#pragma unroll 4
        for (int k = 0; k < SS; k += 4) {
            a0 = fmaf(arow[k + 0], W_at[(k + 0) * SS + c], a0);
            a1 = fmaf(arow[k + 1], W_at[(k + 1) * SS + c], a1);
            a2 = fmaf(arow[k + 2], W_at[(k + 2) * SS + c], a2);
            a3 = fmaf(arow[k + 3], W_at[(k + 3) * SS + c], a3);
        }
        g_Wc[r * SS + c] = (a0 + a1) + (a2 + a3);
    } else {
        g_hbias[c] = 0.5f * b_b0[c];
        for (int i = c; i < GG * 3; i += 256) g_sum[i] = 0.f;
        for (int i = c; i < GG; i += 256)     g_cnt[i] = 0.f;
    }
}

// ============================================================
// Launch 2 — k_possum
// ============================================================
__global__ void k_possum(const float* __restrict__ pos,
                         const int* __restrict__ batch) {
    int n = blockIdx.x * blockDim.x + threadIdx.x;
    if (n >= NN) return;
    int b = batch[n];
    atomicAdd(&g_sum[b * 3 + 0], pos[n * 3 + 0]);
    atomicAdd(&g_sum[b * 3 + 1], pos[n * 3 + 1]);
    atomicAdd(&g_sum[b * 3 + 2], pos[n * 3 + 2]);
    atomicAdd(&g_cnt[b], 1.0f);
}

// ============================================================
// Launch 3 — k_center_h2
// ============================================================
__global__ void __launch_bounds__(256) k_center_h2(const float* __restrict__ pos,
                                                   const int* __restrict__ batch,
                                                   const float* __restrict__ x,
                                                   float* __restrict__ out) {
    if (blockIdx.x < 40) {
        int n = blockIdx.x * 256 + threadIdx.x;
        if (n >= NN) return;
        int b = batch[n];
        float inv = 1.0f / fmaxf(g_cnt[b], 1.0f);
#pragma unroll
        for (int k = 0; k < 3; k++) {
            float v = pos[n * 3 + k] - g_sum[b * 3 + k] * inv;
            g_posc[n * 3 + k] = v;
            out[OFF_CP + n * 3 + k] = v;
            out[OFF_CE0 + n * 3 + k] = 0.f;
        }
    } else {
        int n = blockIdx.x - 40;
        int c = threadIdx.x;
        __shared__ float xs[NAn];
        __shared__ int bsh;
        if (c < NAn) xs[c] = x[n * NAn + c];
        if (c == 0) bsh = batch[n];
        __syncthreads();
        float acc = g_temb2[bsh * SS + c];
#pragma unroll
        for (int k = 0; k < NAn; k++) acc = fmaf(xs[k], g_Wc[k * SS + c], acc);
        g_bufA[n * SS + c] = acc;
    }
}

// ============================================================
// Launches 4,5 — fp32 GEMM, 64x128 tile, BK=16, double-buffered,
// packed f32x2 inner loop (16 FFMA2 per k per thread).
// ACT: 0 = bias only, 1 = bias + silu
// ============================================================
template <int ACT>
__global__ void __launch_bounds__(256) k_gemm64(const float* __restrict__ A,
                                                const float* __restrict__ W,
                                                const float* __restrict__ bias,
                                                float* __restrict__ C) {
    __shared__ float As[2][16][68];
    __shared__ float Bs[2][16][128];
    const int tid = threadIdx.x;
    const int row0 = blockIdx.y * 64;
    const int col0 = blockIdx.x * 128;
    const int ar = tid >> 2;
    const int ak = (tid & 3) * 4;
    const int bk = tid >> 4;
    const int bc = (tid & 15) * 8;
    const int ty = tid >> 4;
    const int tx = tid & 15;
    const int arow = row0 + ar;

    {
        float4 av = make_float4(0.f, 0.f, 0.f, 0.f);
        if (arow < NN) av = *(const float4*)&A[(size_t)arow * SS + ak];
        As[0][ak + 0][ar] = av.x;
        As[0][ak + 1][ar] = av.y;
        As[0][ak + 2][ar] = av.z;
        As[0][ak + 3][ar] = av.w;
        *(float4*)&Bs[0][bk][bc]     = *(const float4*)&W[(size_t)bk * SS + col0 + bc];
        *(float4*)&Bs[0][bk][bc + 4] = *(const float4*)&W[(size_t)bk * SS + col0 + bc + 4];
    }
    __syncthreads();

    ull accp[4][4];
#pragma unroll
    for (int i = 0; i < 4; i++)
#pragma unroll
        for (int m = 0; m < 4; m++) accp[i][m] = 0ull;

    for (int k0 = 0; k0 < SS; k0 += 16) {
        const int buf = (k0 >> 4) & 1;
        const bool more = (k0 + 16 < SS);
        float4 nav = make_float4(0.f, 0.f, 0.f, 0.f);
        float4 nbv0, nbv1;
        if (more) {
            if (arow < NN) nav = *(const float4*)&A[(size_t)arow * SS + k0 + 16 + ak];
            nbv0 = *(const float4*)&W[(size_t)(k0 + 16 + bk) * SS + col0 + bc];
            nbv1 = *(const float4*)&W[(size_t)(k0 + 16 + bk) * SS + col0 + bc + 4];
        }
#pragma unroll
        for (int k = 0; k < 16; k++) {
            float4 a4 = *(const float4*)&As[buf][k][ty * 4];
            ulonglong2 b01 = *(const ulonglong2*)&Bs[buf][k][tx * 4];
            ulonglong2 b23 = *(const ulonglong2*)&Bs[buf][k][64 + tx * 4];
            ull ap0 = f2pk(a4.x, a4.x);
            ull ap1 = f2pk(a4.y, a4.y);
            ull ap2 = f2pk(a4.z, a4.z);
            ull ap3 = f2pk(a4.w, a4.w);
            accp[0][0] = f2fma(ap0, b01.x, accp[0][0]);
            accp[0][1] = f2fma(ap0, b01.y, accp[0][1]);
            accp[0][2] = f2fma(ap0, b23.x, accp[0][2]);
            accp[0][3] = f2fma(ap0, b23.y, accp[0][3]);
            accp[1][0] = f2fma(ap1, b01.x, accp[1][0]);
            accp[1][1] = f2fma(ap1, b01.y, accp[1][1]);
            accp[1][2] = f2fma(ap1, b23.x, accp[1][2]);
            accp[1][3] = f2fma(ap1, b23.y, accp[1][3]);
            accp[2][0] = f2fma(ap2, b01.x, accp[2][0]);
            accp[2][1] = f2fma(ap2, b01.y, accp[2][1]);
            accp[2][2] = f2fma(ap2, b23.x, accp[2][2]);
            accp[2][3] = f2fma(ap2, b23.y, accp[2][3]);
            accp[3][0] = f2fma(ap3, b01.x, accp[3][0]);
            accp[3][1] = f2fma(ap3, b01.y, accp[3][1]);
            accp[3][2] = f2fma(ap3, b23.x, accp[3][2]);
            accp[3][3] = f2fma(ap3, b23.y, accp[3][3]);
        }
        if (more) {
            As[buf ^ 1][ak + 0][ar] = nav.x;
            As[buf ^ 1][ak + 1][ar] = nav.y;
            As[buf ^ 1][ak + 2][ar] = nav.z;
            As[buf ^ 1][ak + 3][ar] = nav.w;
            *(float4*)&Bs[buf ^ 1][bk][bc]     = nbv0;
            *(float4*)&Bs[buf ^ 1][bk][bc + 4] = nbv1;
            __syncthreads();
        }
    }

#pragma unroll
    for (int i = 0; i < 4; i++) {
        int row = row0 + ty * 4 + i;
        if (row >= NN) continue;
#pragma unroll
        for (int half = 0; half < 2; half++) {
            int col = col0 + half * 64 + tx * 4;
            float4 v;
            f2upk(accp[i][half * 2 + 0], v.x, v.y);
            f2upk(accp[i][half * 2 + 1], v.z, v.w);
            v.x += bias[col + 0];
            v.y += bias[col + 1];
            v.z += bias[col + 2];
            v.w += bias[col + 3];
            if (ACT == 1) {
                v.x = __fdividef(v.x, 1.0f + __expf(-v.x));
                v.y = __fdividef(v.y, 1.0f + __expf(-v.y));
                v.z = __fdividef(v.z, 1.0f + __expf(-v.z));
                v.w = __fdividef(v.w, 1.0f + __expf(-v.w));
            }
            *(float4*)&C[(size_t)row * SS + col] = v;
        }
    }
}

// ============================================================
// Launch 6 — k_tail (fused, 128-thread blocks):
//   global edges: packed f32x2 MLP, split reduction,
//   idx prefetch 2 ahead, u/pos prefetch 1 ahead
// ============================================================
__global__ void __launch_bounds__(128, 3) k_tail(const int* __restrict__ eig,
                                                 const float* __restrict__ u,
                                                 const float* __restrict__ W_b0,
                                                 const float* __restrict__ W_b1,
                                                 const float* __restrict__ b_b1,
                                                 const float* __restrict__ h3,
                                                 const float* __restrict__ W_atoms,
                                                 const float* __restrict__ b_atoms,
                                                 const int* __restrict__ eil,
                                                 float* __restrict__ out) {
    const int blk = blockIdx.x;
    const int tid = threadIdx.x;
    const int lane = tid & 31;

    if (blk < GBLK) {
        // ---------------- global edges ----------------
        const int slot = blk * 4 + (tid >> 5);
        const int ch0 = lane * 8;

        ull wb1p[8][5];
        float wd[8];
#pragma unroll
        for (int k = 0; k < 8; k++) {
            wd[k] = W_b0[SS * SS + ch0 + k];
#pragma unroll
            for (int m = 0; m < 5; m++)
                wb1p[k][m] = f2pk(W_b1[(ch0 + k) * 10 + 2 * m],
                                  W_b1[(ch0 + k) * 10 + 2 * m + 1]);
        }
        float bb[5];
        {
            int base = (lane < 16) ? 0 : 5;
#pragma unroll
            for (int g = 0; g < 5; g++) bb[g] = b_b1[base + g];
        }

        int e = slot;
        if (e >= EGn) return;
        int j1 = eig[e];
        int i1 = eig[EGn + e];
        ulonglong2 UA0 = *(const ulonglong2*)(u + (size_t)i1 * SS + ch0);
        ulonglong2 UA1 = *(const ulonglong2*)(u + (size_t)i1 * SS + ch0 + 4);
        ulonglong2 UC0 = *(const ulonglong2*)(u + (size_t)j1 * SS + ch0);
        ulonglong2 UC1 = *(const ulonglong2*)(u + (size_t)j1 * SS + ch0 + 4);
        float pix1 = g_posc[i1 * 3 + 0], piy1 = g_posc[i1 * 3 + 1], piz1 = g_posc[i1 * 3 + 2];
        float pjx1 = g_posc[j1 * 3 + 0], pjy1 = g_posc[j1 * 3 + 1], pjz1 = g_posc[j1 * 3 + 2];
        int e2 = e + NS;
        int j2 = 0, i2 = 0;
        if (e2 < EGn) { j2 = eig[e2]; i2 = eig[EGn + e2]; }

        while (e < EGn) {
            int e3 = e2 + NS;
            int j3 = 0, i3 = 0;
            if (e3 < EGn) { j3 = eig[e3]; i3 = eig[EGn + e3]; }
            ulonglong2 UB0 = make_ulonglong2(0, 0), UB1 = UB0, UD0 = UB0, UD1 = UB0;
            float pix2 = 0.f, piy2 = 0.f, piz2 = 0.f, pjx2 = 0.f, pjy2 = 0.f, pjz2 = 0.f;
            if (e2 < EGn) {
                UB0 = *(const ulonglong2*)(u + (size_t)i2 * SS + ch0);
                UB1 = *(const ulonglong2*)(u + (size_t)i2 * SS + ch0 + 4);
                UD0 = *(const ulonglong2*)(u + (size_t)j2 * SS + ch0);
                UD1 = *(const ulonglong2*)(u + (size_t)j2 * SS + ch0 + 4);
                pix2 = g_posc[i2 * 3 + 0]; piy2 = g_posc[i2 * 3 + 1]; piz2 = g_posc[i2 * 3 + 2];
                pjx2 = g_posc[j2 * 3 + 0]; pjy2 = g_posc[j2 * 3 + 1]; pjz2 = g_posc[j2 * 3 + 2];
            }

            float rx = pix1 - pjx1, ry = piy1 - pjy1, rz = piz1 - pjz1;
            float ss = rx * rx + ry * ry + rz * rz;
            float db = sqrtf(ss);
            if (lane == 0) {
                out[OFF_AG + e] = pix1 * pjx1 + piy1 * pjy1 + piz1 * pjz1;
                float inv = rsqrtf(fmaxf(ss, 1e-6f));
                out[OFF_RNG + 3 * e + 0] = rx * inv;
                out[OFF_RNG + 3 * e + 1] = ry * inv;
                out[OFF_RNG + 3 * e + 2] = rz * inv;
            }

            ull hp[4];
            hp[0] = f2add(UA0.x, UC0.x);
            hp[1] = f2add(UA0.y, UC0.y);
            hp[2] = f2add(UA1.x, UC1.x);
            hp[3] = f2add(UA1.y, UC1.y);
            float h[8];
            f2upk(hp[0], h[0], h[1]);
            f2upk(hp[1], h[2], h[3]);
            f2upk(hp[2], h[4], h[5]);
            f2upk(hp[3], h[6], h[7]);

            ull accp[5] = {0ull, 0ull, 0ull, 0ull, 0ull};
#pragma unroll
            for (int k = 0; k < 8; k++) {
                float pre = fmaf(db, wd[k], h[k]);
                float hv = __fdividef(pre, 1.0f + __expf(-pre));
                ull hvp = f2pk(hv, hv);
#pragma unroll
                for (int m = 0; m < 5; m++) accp[m] = f2fma(hvp, wb1p[k][m], accp[m]);
            }

            float acc[10];
#pragma unroll
            for (int m = 0; m < 5; m++) f2upk(accp[m], acc[2 * m], acc[2 * m + 1]);

#pragma unroll
            for (int o = 0; o < 10; o++)
                acc[o] += __shfl_xor_sync(0xffffffffu, acc[o], 16);
            float v[5];
#pragma unroll
            for (int g = 0; g < 5; g++) v[g] = (lane < 16) ? acc[g] : acc[g + 5];
#pragma unroll
            for (int off = 8; off > 0; off >>= 1) {
#pragma unroll
                for (int g = 0; g < 5; g++)
                    v[g] += __shfl_xor_sync(0xffffffffu, v[g], off);
            }
            if (lane == 0) {
#pragma unroll
                for (int g = 0; g < 5; g++)
                    out[OFF_BP + (size_t)e * 5 + g] = v[g] + bb[g];
            } else if (lane == 16) {
#pragma unroll
                for (int g = 0; g < 5; g++)
                    out[OFF_BE + (size_t)e * 5 + g] = v[g] + bb[g];
            }

            e = e2; i1 = i2; j1 = j2;
            UA0 = UB0; UA1 = UB1; UC0 = UD0; UC1 = UD1;
            pix1 = pix2; piy1 = piy2; piz1 = piz2;
            pjx1 = pjx2; pjy1 = pjy2; pjz1 = pjz2;
            e2 = e3; i2 = i3; j2 = j3;
        }
    } else if (blk < GBLK + ABLK) {
        // ---------------- atoms ----------------
        int w = (blk - GBLK) * 4 + (tid >> 5);
        if (w >= NN) return;
        float acc = b_atoms[lane];
        for (int k0 = 0; k0 < SS; k0 += 32) {
            float hv = h3[(size_t)w * SS + k0 + lane];
#pragma unroll
            for (int kk = 0; kk < 32; kk++) {
                float h = __shfl_sync(0xffffffffu, hv, kk);
                acc = fmaf(h, W_atoms[(k0 + kk) * 32 + lane], acc);
            }
        }
        if (lane < NAn) out[OFF_AE + w * NAn + lane] = acc;
        else            out[OFF_AP + w * NAn + (lane - NAn)] = acc;
    } else {
        // ---------------- local edges ----------------
        int e = (blk - GBLK - ABLK) * 128 + tid;
        if (e >= ELn) return;
        int s = eil[e];
        int tg = eil[ELn + e];
        float rx = g_posc[tg * 3 + 0] - g_posc[s * 3 + 0];
        float ry = g_posc[tg * 3 + 1] - g_posc[s * 3 + 1];
        float rz = g_posc[tg * 3 + 2] - g_posc[s * 3 + 2];
        float ss = rx * rx + ry * ry + rz * rz;
        float sc = fmaxf(ss, 1e-6f);
        float d = sqrtf(sc);
        out[OFF_DL + e] = d;
        float inv = rsqrtf(sc);
        out[OFF_RNL + 3 * e + 0] = rx * inv;
        out[OFF_RNL + 3 * e + 1] = ry * inv;
        out[OFF_RNL + 3 * e + 2] = rz * inv;
    }
}

// ============================================================
// Host launcher
// ============================================================
extern "C" void kernel_launch(void* const* d_in, const int* in_sizes, int n_in,
                              void* d_out, int out_size) {
    int iX, iT, iPOS, iWT, iBT, iWA, iBA, iWAT, iBAT, iWSH, iBSH,
        iWB0, iBB0, iWB1, iBB1, iWATM, iBATM, iEIL, iEIG, iBATCH;
    if (in_sizes[3] == 2 * ELn) {
        iX = 0; iT = 1; iPOS = 2; iEIL = 3; iEIG = 4; iBATCH = 6;
        iWT = 7; iBT = 8; iWA = 9; iBA = 10; iWAT = 11; iBAT = 12;
        iWSH = 13; iBSH = 14; iWB0 = 15; iBB0 = 16; iWB1 = 17; iBB1 = 18;
        iWATM = 20; iBATM = 21;
    } else {
        iX = 0; iT = 1; iPOS = 2; iWT = 4; iBT = 5; iWA = 6; iBA = 7;
        iWAT = 8; iBAT = 9; iWSH = 10; iBSH = 11; iWB0 = 12; iBB0 = 13;
        iWB1 = 14; iBB1 = 15; iWATM = 17; iBATM = 18;
        iEIL = 19; iEIG = 20; iBATCH = 21;
    }

    const float* x       = (const float*)d_in[iX];
    const float* t       = (const float*)d_in[iT];
    const float* pos     = (const float*)d_in[iPOS];
    const float* W_time  = (const float*)d_in[iWT];
    const float* b_time  = (const float*)d_in[iBT];
    const float* W_atom  = (const float*)d_in[iWA];
    const float* b_atom  = (const float*)d_in[iBA];
    const float* W_at    = (const float*)d_in[iWAT];
    const float* b_at    = (const float*)d_in[iBAT];
    const float* W_sh    = (const float*)d_in[iWSH];
    const float* b_sh    = (const float*)d_in[iBSH];
    const float* W_b0    = (const float*)d_in[iWB0];
    const float* b_b0    = (const float*)d_in[iBB0];
    const float* W_b1    = (const float*)d_in[iWB1];
    const float* b_b1    = (const float*)d_in[iBB1];
    const float* W_atoms = (const float*)d_in[iWATM];
    const float* b_atoms = (const float*)d_in[iBATM];
    const int* eil       = (const int*)d_in[iEIL];
    const int* eig       = (const int*)d_in[iEIG];
    const int* batch     = (const int*)d_in[iBATCH];
    float* out = (float*)d_out;

    float *bufA, *bufB, *hbias;
    cudaGetSymbolAddress((void**)&bufA, g_bufA);
    cudaGetSymbolAddress((void**)&bufB, g_bufB);
    cudaGetSymbolAddress((void**)&hbias, g_hbias);

    // 1
    k_pre<<<GG + NAn + 1, 256>>>(t, W_time, b_time, b_atom, W_at, b_at, W_atom, b_b0);
    // 2
    k_possum<<<(NN + 255) / 256, 256>>>(pos, batch);
    // 3
    k_center_h2<<<40 + NN, 256>>>(pos, batch, x, out);
    // 4,5
    dim3 gg(2, (NN + 63) / 64);
    k_gemm64<1><<<gg, 256>>>(bufA, W_sh, b_sh, bufB);      // h3 -> bufB
    k_gemm64<0><<<gg, 256>>>(bufB, W_b0, hbias, bufA);     // u + 0.5*b_b0 -> bufA
    // 6 — fused tail
    k_tail<<<GBLK + ABLK + LBLK, 128>>>(eig, bufA, W_b0, W_b1, b_b1,
                                        bufB, W_atoms, b_atoms, eil, out);
}